// round 7
// baseline (speedup 1.0000x reference)
#include <cuda_runtime.h>
#include <cuda_bf16.h>
#include <math.h>
#include <cstdint>

#define B_   2
#define S_   2048
#define E_   2048
#define H_   16
#define KVH_ 4
#define HD_  128
#define REP_ 4
#define M_   (B_*S_)     // 4096
#define NQKV 3072

// ---------------------------------------------------------------------------
// Scratch (__device__ globals; no allocations allowed)
// ---------------------------------------------------------------------------
__device__ __nv_bfloat16 g_xhi[M_*E_],  g_xlo[M_*E_];
__device__ __nv_bfloat16 g_aohi[M_*E_], g_aolo[M_*E_];
__device__ __nv_bfloat16 g_wqT_hi[E_*E_],        g_wqT_lo[E_*E_];
__device__ __nv_bfloat16 g_wkT_hi[KVH_*HD_*E_],  g_wkT_lo[KVH_*HD_*E_];
__device__ __nv_bfloat16 g_wvT_hi[KVH_*HD_*E_],  g_wvT_lo[KVH_*HD_*E_];
__device__ __nv_bfloat16 g_woT_hi[E_*E_],        g_woT_lo[E_*E_];

// flash operand layouts: Q [B][H][S][HD], K/V [B][KVH][S][HD]
__device__ __nv_bfloat16 g_Qbh[M_*H_*HD_],   g_Qbl[M_*H_*HD_];
__device__ __nv_bfloat16 g_Kbh[M_*KVH_*HD_], g_Kbl[M_*KVH_*HD_];
__device__ __nv_bfloat16 g_Vbh[M_*KVH_*HD_], g_Vbl[M_*KVH_*HD_];

// ---------------------------------------------------------------------------
// PTX helpers (non-'a' ISA only: mma.sync / ldmatrix / cp.async)
// ---------------------------------------------------------------------------
__device__ __forceinline__ uint32_t smem_to_u32(const void* p) {
    uint32_t a;
    asm("{ .reg .u64 t; cvta.to.shared.u64 t, %1; cvt.u32.u64 %0, t; }" : "=r"(a) : "l"(p));
    return a;
}
__device__ __forceinline__ void cp_async16(uint32_t saddr, const void* gptr) {
    asm volatile("cp.async.cg.shared.global [%0], [%1], 16;\n" :: "r"(saddr), "l"(gptr));
}
#define CP_COMMIT() asm volatile("cp.async.commit_group;\n" ::: "memory")
#define CP_WAIT(n)  asm volatile("cp.async.wait_group %0;\n" :: "n"(n) : "memory")

__device__ __forceinline__ void ldmatrix_x4(uint32_t* r, uint32_t addr) {
    asm volatile("ldmatrix.sync.aligned.m8n8.x4.shared.b16 {%0,%1,%2,%3}, [%4];\n"
                 : "=r"(r[0]), "=r"(r[1]), "=r"(r[2]), "=r"(r[3]) : "r"(addr));
}
__device__ __forceinline__ void ldmatrix_x4_trans(uint32_t* r, uint32_t addr) {
    asm volatile("ldmatrix.sync.aligned.m8n8.x4.trans.shared.b16 {%0,%1,%2,%3}, [%4];\n"
                 : "=r"(r[0]), "=r"(r[1]), "=r"(r[2]), "=r"(r[3]) : "r"(addr));
}
__device__ __forceinline__ void mma_bf16(float* c, const uint32_t* a, const uint32_t* b) {
    asm volatile(
        "mma.sync.aligned.m16n8k16.row.col.f32.bf16.bf16.f32 "
        "{%0,%1,%2,%3}, {%4,%5,%6,%7}, {%8,%9}, {%0,%1,%2,%3};\n"
        : "+f"(c[0]), "+f"(c[1]), "+f"(c[2]), "+f"(c[3])
        : "r"(a[0]), "r"(a[1]), "r"(a[2]), "r"(a[3]), "r"(b[0]), "r"(b[1]));
}
__device__ __forceinline__ void split2(float a, float b, uint32_t& hi, uint32_t& lo) {
    __nv_bfloat162 h = __floats2bfloat162_rn(a, b);
    __nv_bfloat162 l = __floats2bfloat162_rn(a - __bfloat162float(h.x),
                                             b - __bfloat162float(h.y));
    hi = *(uint32_t*)&h;
    lo = *(uint32_t*)&l;
}

// ---------------------------------------------------------------------------
// Conversion kernels
// ---------------------------------------------------------------------------
__global__ void convert_hilo_kernel(const float* __restrict__ in,
                                    __nv_bfloat16* __restrict__ hi,
                                    __nv_bfloat16* __restrict__ lo, int n4)
{
    int i = blockIdx.x * blockDim.x + threadIdx.x;
    if (i >= n4) return;
    float4 v = ((const float4*)in)[i];
    float a[4] = {v.x, v.y, v.z, v.w};
    __nv_bfloat16 h[4], l[4];
    #pragma unroll
    for (int j = 0; j < 4; j++) {
        h[j] = __float2bfloat16_rn(a[j]);
        l[j] = __float2bfloat16_rn(a[j] - __bfloat162float(h[j]));
    }
    __nv_bfloat162* ph = (__nv_bfloat162*)(hi + 4 * (size_t)i);
    __nv_bfloat162* pl = (__nv_bfloat162*)(lo + 4 * (size_t)i);
    ph[0] = __nv_bfloat162{h[0], h[1]}; ph[1] = __nv_bfloat162{h[2], h[3]};
    pl[0] = __nv_bfloat162{l[0], l[1]}; pl[1] = __nv_bfloat162{l[2], l[3]};
}

// W[K x N] fp32 -> WT_hi/lo[N x K] bf16
__global__ void transpose_hilo_kernel(const float* __restrict__ W,
                                      __nv_bfloat16* __restrict__ Thi,
                                      __nv_bfloat16* __restrict__ Tlo,
                                      int K, int N)
{
    __shared__ float tile[32][33];
    int n0 = blockIdx.x * 32, k0 = blockIdx.y * 32;
    int tx = threadIdx.x, ty = threadIdx.y;
    #pragma unroll
    for (int r = 0; r < 4; r++)
        tile[ty + r * 8][tx] = W[(size_t)(k0 + ty + r * 8) * N + n0 + tx];
    __syncthreads();
    #pragma unroll
    for (int r = 0; r < 4; r++) {
        float v = tile[tx][ty + r * 8];
        __nv_bfloat16 h = __float2bfloat16_rn(v);
        __nv_bfloat16 l = __float2bfloat16_rn(v - __bfloat162float(h));
        size_t o = (size_t)(n0 + ty + r * 8) * K + k0 + tx;
        Thi[o] = h; Tlo[o] = l;
    }
}

// ---------------------------------------------------------------------------
// Split-bf16 HMMA GEMM mainloop: 128x128 tile, K chunks of 64, 3 stages.
// ---------------------------------------------------------------------------
#define GBK      64
#define GROWB    144                   // 128B data + 16 pad
#define GARR     (128 * GROWB)         // 18432
#define GSTAGE   (4 * GARR)            // 73728
#define GSTAGES  3
#define GSMEM    (GSTAGES * GSTAGE)    // 221184

__device__ __forceinline__ void gemm_mainloop(
    const __nv_bfloat16* __restrict__ Ahi, const __nv_bfloat16* __restrict__ Alo,
    const __nv_bfloat16* __restrict__ Bhi, const __nv_bfloat16* __restrict__ Blo,
    int rowA0, int rowB0, int K, uint32_t sb, int tid, float acc[4][4][4])
{
    const int wid  = tid >> 5;
    const int lane = tid & 31;
    const int warp_m = wid >> 2;
    const int warp_n = wid & 3;
    const int nchunks = K / GBK;

    const int m_lr = lane & 15;          // ldmatrix x4 row within 16
    const int m_kc = (lane >> 4) * 8;    // ldmatrix x4 K-col half

    auto load_stage = [&](int chunk, int stage) {
        const int k0 = chunk * GBK;
        uint32_t s = sb + stage * GSTAGE;
        const __nv_bfloat16* ptrs[4] = {Ahi, Alo, Bhi, Blo};
        const int rows[4] = {rowA0, rowA0, rowB0, rowB0};
        #pragma unroll
        for (int arr = 0; arr < 4; arr++) {
            #pragma unroll
            for (int t = 0; t < 4; t++) {
                int u = t * 256 + tid;
                int r = u >> 3, c = u & 7;
                cp_async16(s + arr * GARR + r * GROWB + c * 16,
                           ptrs[arr] + (size_t)(rows[arr] + r) * K + k0 + c * 8);
            }
        }
    };

    #pragma unroll
    for (int s = 0; s < GSTAGES; s++) { load_stage(s, s); CP_COMMIT(); }

    for (int i = 0; i < nchunks; i++) {
        CP_WAIT(GSTAGES - 1);
        __syncthreads();

        const int stage = i % GSTAGES;
        const uint32_t sAhi = sb + stage * GSTAGE;
        const uint32_t sAlo = sAhi + GARR;
        const uint32_t sBhi = sAlo + GARR;
        const uint32_t sBlo = sBhi + GARR;

        #pragma unroll
        for (int ks = 0; ks < 4; ks++) {
            const int kb = ks * 32;
            uint32_t ah[4][4], al[4][4], bh[4][2], bl[4][2];
            #pragma unroll
            for (int mt = 0; mt < 4; mt++) {
                uint32_t aoff = (uint32_t)(warp_m * 64 + mt * 16 + m_lr) * GROWB + m_kc * 2 + kb;
                ldmatrix_x4(ah[mt], sAhi + aoff);
                ldmatrix_x4(al[mt], sAlo + aoff);
            }
            #pragma unroll
            for (int np = 0; np < 2; np++) {
                uint32_t t[4];
                uint32_t boff = (uint32_t)(warp_n * 32 + np * 16 + m_lr) * GROWB + m_kc * 2 + kb;
                ldmatrix_x4(t, sBhi + boff);
                bh[np*2][0] = t[0]; bh[np*2][1] = t[2];
                bh[np*2+1][0] = t[1]; bh[np*2+1][1] = t[3];
                ldmatrix_x4(t, sBlo + boff);
                bl[np*2][0] = t[0]; bl[np*2][1] = t[2];
                bl[np*2+1][0] = t[1]; bl[np*2+1][1] = t[3];
            }
            #pragma unroll
            for (int mt = 0; mt < 4; mt++)
                #pragma unroll
                for (int nt = 0; nt < 4; nt++) {
                    mma_bf16(acc[mt][nt], ah[mt], bh[nt]);
                    mma_bf16(acc[mt][nt], ah[mt], bl[nt]);
                    mma_bf16(acc[mt][nt], al[mt], bh[nt]);
                }
        }
        __syncthreads();
        if (i + GSTAGES < nchunks) load_stage(i + GSTAGES, stage);
        CP_COMMIT();
    }
}

// Generic GEMM (O projection): C[M,N] row stride N
__global__ void __launch_bounds__(256, 1)
gemm_bf16x3_kernel(const __nv_bfloat16* __restrict__ Ahi,
                   const __nv_bfloat16* __restrict__ Alo,
                   const __nv_bfloat16* __restrict__ Bhi,
                   const __nv_bfloat16* __restrict__ Blo,
                   const float* __restrict__ bias,
                   float* __restrict__ C,
                   int M, int N, int K)
{
    extern __shared__ char smem[];
    const uint32_t sb = smem_to_u32(smem);
    const int tid  = threadIdx.x;
    const int wid  = tid >> 5;
    const int lane = tid & 31;
    const int rowA0 = blockIdx.y * 128;
    const int rowB0 = blockIdx.x * 128;

    float acc[4][4][4];
    #pragma unroll
    for (int i = 0; i < 4; i++)
        #pragma unroll
        for (int j = 0; j < 4; j++)
            #pragma unroll
            for (int k = 0; k < 4; k++) acc[i][j][k] = 0.0f;

    gemm_mainloop(Ahi, Alo, Bhi, Blo, rowA0, rowB0, K, sb, tid, acc);

    const int warp_m = wid >> 2, warp_n = wid & 3;
    #pragma unroll
    for (int mt = 0; mt < 4; mt++)
        #pragma unroll
        for (int nt = 0; nt < 4; nt++) {
            int row = rowA0 + warp_m * 64 + mt * 16 + (lane >> 2);
            int col = rowB0 + warp_n * 32 + nt * 8 + (lane & 3) * 2;
            float2 b01 = *(const float2*)&bias[col];
            float2 o0 = {acc[mt][nt][0] + b01.x, acc[mt][nt][1] + b01.y};
            float2 o1 = {acc[mt][nt][2] + b01.x, acc[mt][nt][3] + b01.y};
            *(float2*)&C[(size_t)row * N + col]       = o0;
            *(float2*)&C[(size_t)(row + 8) * N + col] = o1;
        }
}

// ---------------------------------------------------------------------------
// Fused QKV projection + bias + RoPE + hi/lo split + flash relayout.
// RoPE freq is nonzero only for d<8 (fp32 powf overflow in reference):
//   freq(d2) = {1, 1e-10, 1e-20, 1e-30} for d2=0..3, else 0.
// For d2>=1, ang <= 2047e-10: sin(ang)=ang and cos(ang)=1 at fp32 precision,
// so only d2==0 (lane&3==0) needs a real sincosf. No powf anywhere.
// ---------------------------------------------------------------------------
__global__ void __launch_bounds__(256, 1)
gemm_qkv_kernel(const __nv_bfloat16* __restrict__ xhi,
                const __nv_bfloat16* __restrict__ xlo,
                const __nv_bfloat16* __restrict__ wqh, const __nv_bfloat16* __restrict__ wql,
                const __nv_bfloat16* __restrict__ wkh, const __nv_bfloat16* __restrict__ wkl,
                const __nv_bfloat16* __restrict__ wvh, const __nv_bfloat16* __restrict__ wvl,
                const float* __restrict__ bq, const float* __restrict__ bk,
                const float* __restrict__ bv,
                __nv_bfloat16* __restrict__ Qbh, __nv_bfloat16* __restrict__ Qbl,
                __nv_bfloat16* __restrict__ Kbh, __nv_bfloat16* __restrict__ Kbl,
                __nv_bfloat16* __restrict__ Vbh, __nv_bfloat16* __restrict__ Vbl)
{
    extern __shared__ char smem[];
    const uint32_t sb = smem_to_u32(smem);
    const int tid  = threadIdx.x;
    const int wid  = tid >> 5;
    const int lane = tid & 31;
    const int cCol = blockIdx.x;         // 0..23
    const int rowA0 = blockIdx.y * 128;

    const __nv_bfloat16 *Bh, *Bl;
    const float* bias;
    int rowB0;
    int mode;                            // 0=Q, 1=K, 2=V
    if (cCol < 16)      { Bh = wqh; Bl = wql; bias = bq; rowB0 = cCol * 128; mode = 0; }
    else if (cCol < 20) { Bh = wkh; Bl = wkl; bias = bk; rowB0 = (cCol - 16) * 128; mode = 1; }
    else                { Bh = wvh; Bl = wvl; bias = bv; rowB0 = (cCol - 20) * 128; mode = 2; }

    float acc[4][4][4];
    #pragma unroll
    for (int i = 0; i < 4; i++)
        #pragma unroll
        for (int j = 0; j < 4; j++)
            #pragma unroll
            for (int k = 0; k < 4; k++) acc[i][j][k] = 0.0f;

    gemm_mainloop(xhi, xlo, Bh, Bl, rowA0, rowB0, E_, sb, tid, acc);

    const int warp_m = wid >> 2, warp_n = wid & 3;
    const int h_or_g = rowB0 >> 7;

    __nv_bfloat16* Oh = (mode == 0) ? Qbh : (mode == 1) ? Kbh : Vbh;
    __nv_bfloat16* Ol = (mode == 0) ? Qbl : (mode == 1) ? Kbl : Vbl;
    const int nheads = (mode == 0) ? H_ : KVH_;
    const float osc  = (mode == 0) ? 0.08838834764831845f : 1.0f;  // 1/sqrt(128)

    // rope lane constants (d2 = lane&3 when warp_n==0, nt==0)
    const int d2 = lane & 3;
    const float freq_tab[4] = {1.0f, 1e-10f, 1e-20f, 1e-30f};
    const float myfreq = freq_tab[d2];
    const bool rope_lane = (mode != 2) && (warp_n == 0);

    #pragma unroll
    for (int mt = 0; mt < 4; mt++)
        #pragma unroll
        for (int nt = 0; nt < 4; nt++) {
            const int row  = rowA0 + warp_m * 64 + mt * 16 + (lane >> 2);
            const int bcol = rowB0 + warp_n * 32 + nt * 8 + (lane & 3) * 2;
            const int d    = bcol & 127;
            float2 b01 = *(const float2*)&bias[bcol];
            #pragma unroll
            for (int rr = 0; rr < 2; rr++) {
                float o0 = acc[mt][nt][rr * 2 + 0] + b01.x;
                float o1 = acc[mt][nt][rr * 2 + 1] + b01.y;
                const int r  = row + rr * 8;
                const int bb = r >> 11;
                const int s  = r & 2047;
                if (rope_lane && nt == 0) {
                    float sn, cs;
                    if (d2 == 0) {
                        sincosf((float)s, &sn, &cs);
                    } else {
                        sn = (float)s * myfreq;   // sin(x)=x at fp32 for x<=2e-7
                        cs = 1.0f;                // cos(x)=1 at fp32
                    }
                    float t0 = o0 * cs - o1 * sn;
                    float t1 = o0 * sn + o1 * cs;
                    o0 = t0; o1 = t1;
                }
                o0 *= osc; o1 *= osc;
                uint32_t hi, lo;
                split2(o0, o1, hi, lo);
                size_t dst = ((size_t)(bb * nheads + h_or_g) * S_ + s) * HD_ + d;
                *(uint32_t*)(Oh + dst) = hi;
                *(uint32_t*)(Ol + dst) = lo;
            }
        }
}

// ---------------------------------------------------------------------------
// Flash attention, split-bf16 HMMA. Br=128, Bc=64, HD=128, 8 warps.
// ---------------------------------------------------------------------------
#define FROWB  272
#define QARR   (128 * FROWB)        // 34816
#define KARR   (64 * FROWB)         // 17408
#define FSTG   (4 * KARR)           // 69632 (Kh,Kl,Vh,Vl)
#define FSMEM  (2 * QARR + 2 * FSTG)  // 208896

__global__ void __launch_bounds__(256, 1)
flash_mma_kernel(const __nv_bfloat16* __restrict__ Qh, const __nv_bfloat16* __restrict__ Ql,
                 const __nv_bfloat16* __restrict__ Kh, const __nv_bfloat16* __restrict__ Kl,
                 const __nv_bfloat16* __restrict__ Vh, const __nv_bfloat16* __restrict__ Vl,
                 __nv_bfloat16* __restrict__ Ohi, __nv_bfloat16* __restrict__ Olo)
{
    extern __shared__ char smem[];
    const uint32_t sb = smem_to_u32(smem);
    const int tid  = threadIdx.x;
    const int lane = tid & 31;
    const int warp = tid >> 5;
    const int qt = (int)gridDim.x - 1 - (int)blockIdx.x;   // heavy tiles first
    const int h = blockIdx.y, b = blockIdx.z;
    const int g  = h >> 2;
    const int q0 = qt * 128;
    const int nkv = 2 * qt + 2;

    const uint32_t sQh = sb, sQl = sb + QARR;
    const uint32_t sKV0 = sb + 2 * QARR;

    const size_t qbase  = ((size_t)(b * H_ + h) * S_ + q0) * HD_;
    const size_t kvbase = ((size_t)(b * KVH_ + g) * S_) * HD_;

    const uint32_t q_off = (uint32_t)(lane & 15) * FROWB + (lane >> 4) * 16;
    const uint32_t k_off = (uint32_t)((lane & 7) | ((lane >> 1) & 8)) * FROWB + ((lane >> 3) & 1) * 16;

    // -- prologue: Q tile (128 rows) + KV stage 0 --
    #pragma unroll
    for (int t = 0; t < 8; t++) {
        int u = t * 256 + tid;                  // 0..2047
        int r = u >> 4, cb = (u & 15) * 16, ce = (u & 15) * 8;
        cp_async16(sQh + r * FROWB + cb, Qh + qbase + (size_t)r * HD_ + ce);
        cp_async16(sQl + r * FROWB + cb, Ql + qbase + (size_t)r * HD_ + ce);
    }
    auto load_kv = [&](int kt, int buf) {
        uint32_t s = sKV0 + buf * FSTG;
        const size_t base = kvbase + (size_t)kt * 64 * HD_;
        #pragma unroll
        for (int t = 0; t < 4; t++) {
            int u = t * 256 + tid;              // 0..1023
            int r = u >> 4, cb = (u & 15) * 16, ce = (u & 15) * 8;
            size_t go = base + (size_t)r * HD_ + ce;
            uint32_t so = r * FROWB + cb;
            cp_async16(s + so,            Kh + go);
            cp_async16(s + KARR + so,     Kl + go);
            cp_async16(s + 2 * KARR + so, Vh + go);
            cp_async16(s + 3 * KARR + so, Vl + go);
        }
    };
    load_kv(0, 0);
    CP_COMMIT();

    float oacc[16][4];
    #pragma unroll
    for (int i = 0; i < 16; i++)
        #pragma unroll
        for (int j = 0; j < 4; j++) oacc[i][j] = 0.0f;
    float m0 = -INFINITY, m1 = -INFINITY, l0 = 0.0f, l1 = 0.0f;

    for (int kt = 0; kt < nkv; kt++) {
        __syncthreads();
        if (kt + 1 < nkv) { load_kv(kt + 1, (kt + 1) & 1); CP_COMMIT(); CP_WAIT(1); }
        else              { CP_WAIT(0); }
        __syncthreads();

        const uint32_t st  = sKV0 + (kt & 1) * FSTG;
        const uint32_t sKh = st, sKl = st + KARR, sVh = st + 2 * KARR, sVl = st + 3 * KARR;

        // ---- S = Q K^T ----
        float sacc[8][4];
        #pragma unroll
        for (int i = 0; i < 8; i++)
            #pragma unroll
            for (int j = 0; j < 4; j++) sacc[i][j] = 0.0f;

        #pragma unroll
        for (int kk = 0; kk < 8; kk++) {
            const uint32_t kb = kk * 32;
            uint32_t qh[4], ql[4];
            ldmatrix_x4(qh, sQh + (uint32_t)warp * 16 * FROWB + q_off + kb);
            ldmatrix_x4(ql, sQl + (uint32_t)warp * 16 * FROWB + q_off + kb);
            #pragma unroll
            for (int np = 0; np < 4; np++) {
                uint32_t kh[4], kl[4];
                ldmatrix_x4(kh, sKh + (uint32_t)np * 16 * FROWB + k_off + kb);
                ldmatrix_x4(kl, sKl + (uint32_t)np * 16 * FROWB + k_off + kb);
                mma_bf16(sacc[2*np],   qh, &kh[0]);
                mma_bf16(sacc[2*np],   qh, &kl[0]);
                mma_bf16(sacc[2*np],   ql, &kh[0]);
                mma_bf16(sacc[2*np+1], qh, &kh[2]);
                mma_bf16(sacc[2*np+1], qh, &kl[2]);
                mma_bf16(sacc[2*np+1], ql, &kh[2]);
            }
        }

        // ---- causal mask (diagonal region spans kv chunks 2qt, 2qt+1) ----
        if (kt >= 2 * qt) {
            const int rg0 = q0 + warp * 16 + (lane >> 2);
            const int cg0 = kt * 64 + (lane & 3) * 2;
            #pragma unroll
            for (int nt = 0; nt < 8; nt++)
                #pragma unroll
                for (int j = 0; j < 4; j++) {
                    int col = cg0 + nt * 8 + (j & 1);
                    int row = rg0 + (j >> 1) * 8;
                    if (col > row) sacc[nt][j] = -INFINITY;
                }
        }

        // ---- online softmax ----
        float mx0 = -INFINITY, mx1 = -INFINITY;
        #pragma unroll
        for (int nt = 0; nt < 8; nt++) {
            mx0 = fmaxf(mx0, fmaxf(sacc[nt][0], sacc[nt][1]));
            mx1 = fmaxf(mx1, fmaxf(sacc[nt][2], sacc[nt][3]));
        }
        mx0 = fmaxf(mx0, __shfl_xor_sync(0xFFFFFFFF, mx0, 1));
        mx0 = fmaxf(mx0, __shfl_xor_sync(0xFFFFFFFF, mx0, 2));
        mx1 = fmaxf(mx1, __shfl_xor_sync(0xFFFFFFFF, mx1, 1));
        mx1 = fmaxf(mx1, __shfl_xor_sync(0xFFFFFFFF, mx1, 2));
        float mn0 = fmaxf(m0, mx0), mn1 = fmaxf(m1, mx1);
        float al0 = __expf(m0 - mn0), al1 = __expf(m1 - mn1);
        m0 = mn0; m1 = mn1;

        float ps0 = 0.0f, ps1 = 0.0f;
        #pragma unroll
        for (int nt = 0; nt < 8; nt++) {
            float p0 = __expf(sacc[nt][0] - mn0);
            float p1 = __expf(sacc[nt][1] - mn0);
            float p2 = __expf(sacc[nt][2] - mn1);
            float p3 = __expf(sacc[nt][3] - mn1);
            sacc[nt][0] = p0; sacc[nt][1] = p1; sacc[nt][2] = p2; sacc[nt][3] = p3;
            ps0 += p0 + p1; ps1 += p2 + p3;
        }
        ps0 += __shfl_xor_sync(0xFFFFFFFF, ps0, 1);
        ps0 += __shfl_xor_sync(0xFFFFFFFF, ps0, 2);
        ps1 += __shfl_xor_sync(0xFFFFFFFF, ps1, 1);
        ps1 += __shfl_xor_sync(0xFFFFFFFF, ps1, 2);
        l0 = l0 * al0 + ps0;
        l1 = l1 * al1 + ps1;

        #pragma unroll
        for (int i = 0; i < 16; i++) {
            oacc[i][0] *= al0; oacc[i][1] *= al0;
            oacc[i][2] *= al1; oacc[i][3] *= al1;
        }

        // ---- O += P V ----
        #pragma unroll
        for (int tk = 0; tk < 4; tk++) {
            uint32_t ah[4], al_[4];
            split2(sacc[2*tk][0],   sacc[2*tk][1],   ah[0], al_[0]);
            split2(sacc[2*tk][2],   sacc[2*tk][3],   ah[1], al_[1]);
            split2(sacc[2*tk+1][0], sacc[2*tk+1][1], ah[2], al_[2]);
            split2(sacc[2*tk+1][2], sacc[2*tk+1][3], ah[3], al_[3]);
            #pragma unroll
            for (int dp = 0; dp < 8; dp++) {
                uint32_t vh[4], vl[4];
                const uint32_t vo = (uint32_t)tk * 16 * FROWB + q_off + dp * 32;
                ldmatrix_x4_trans(vh, sVh + vo);
                ldmatrix_x4_trans(vl, sVl + vo);
                mma_bf16(oacc[2*dp],   ah,  &vh[0]);
                mma_bf16(oacc[2*dp],   ah,  &vl[0]);
                mma_bf16(oacc[2*dp],   al_, &vh[0]);
                mma_bf16(oacc[2*dp+1], ah,  &vh[2]);
                mma_bf16(oacc[2*dp+1], ah,  &vl[2]);
                mma_bf16(oacc[2*dp+1], al_, &vh[2]);
            }
        }
    }

    // ---- epilogue: O / l -> hi/lo bf16 at [b][s][h*HD] ----
    const float il0 = 1.0f / l0, il1 = 1.0f / l1;
    const int r0 = q0 + warp * 16 + (lane >> 2);
    const int c0 = h * HD_ + (lane & 3) * 2;
    #pragma unroll
    for (int nt = 0; nt < 16; nt++) {
        float o0 = oacc[nt][0] * il0, o1 = oacc[nt][1] * il0;
        float o2 = oacc[nt][2] * il1, o3 = oacc[nt][3] * il1;
        uint32_t h0, l0r, h1, l1r;
        split2(o0, o1, h0, l0r);
        split2(o2, o3, h1, l1r);
        size_t i0 = (size_t)(b * S_ + r0)     * E_ + c0 + nt * 8;
        size_t i1 = (size_t)(b * S_ + r0 + 8) * E_ + c0 + nt * 8;
        *(uint32_t*)(Ohi + i0) = h0; *(uint32_t*)(Olo + i0) = l0r;
        *(uint32_t*)(Ohi + i1) = h1; *(uint32_t*)(Olo + i1) = l1r;
    }
}

// ---------------------------------------------------------------------------
extern "C" void kernel_launch(void* const* d_in, const int* in_sizes, int n_in,
                              void* d_out, int out_size)
{
    const float* x  = (const float*)d_in[0];
    const float* wq = (const float*)d_in[1];
    const float* bq = (const float*)d_in[2];
    const float* wk = (const float*)d_in[3];
    const float* bk = (const float*)d_in[4];
    const float* wv = (const float*)d_in[5];
    const float* bv = (const float*)d_in[6];
    const float* wo = (const float*)d_in[7];
    const float* bo = (const float*)d_in[8];
    float* out = (float*)d_out;

    __nv_bfloat16 *xhi, *xlo, *aohi, *aolo;
    __nv_bfloat16 *wqh, *wql, *wkh, *wkl, *wvh, *wvl, *woh, *wol;
    __nv_bfloat16 *qbh, *qbl, *kbh, *kbl, *vbh, *vbl;
    cudaGetSymbolAddress((void**)&xhi,  g_xhi);
    cudaGetSymbolAddress((void**)&xlo,  g_xlo);
    cudaGetSymbolAddress((void**)&aohi, g_aohi);
    cudaGetSymbolAddress((void**)&aolo, g_aolo);
    cudaGetSymbolAddress((void**)&wqh, g_wqT_hi);
    cudaGetSymbolAddress((void**)&wql, g_wqT_lo);
    cudaGetSymbolAddress((void**)&wkh, g_wkT_hi);
    cudaGetSymbolAddress((void**)&wkl, g_wkT_lo);
    cudaGetSymbolAddress((void**)&wvh, g_wvT_hi);
    cudaGetSymbolAddress((void**)&wvl, g_wvT_lo);
    cudaGetSymbolAddress((void**)&woh, g_woT_hi);
    cudaGetSymbolAddress((void**)&wol, g_woT_lo);
    cudaGetSymbolAddress((void**)&qbh, g_Qbh);
    cudaGetSymbolAddress((void**)&qbl, g_Qbl);
    cudaGetSymbolAddress((void**)&kbh, g_Kbh);
    cudaGetSymbolAddress((void**)&kbl, g_Kbl);
    cudaGetSymbolAddress((void**)&vbh, g_Vbh);
    cudaGetSymbolAddress((void**)&vbl, g_Vbl);

    // conversions
    {
        int n4 = M_ * E_ / 4;
        convert_hilo_kernel<<<(n4 + 255) / 256, 256>>>(x, xhi, xlo, n4);
        dim3 blk(32, 8);
        transpose_hilo_kernel<<<dim3(E_ / 32, E_ / 32), blk>>>(wq, wqh, wql, E_, E_);
        transpose_hilo_kernel<<<dim3((KVH_ * HD_) / 32, E_ / 32), blk>>>(wk, wkh, wkl, E_, KVH_ * HD_);
        transpose_hilo_kernel<<<dim3((KVH_ * HD_) / 32, E_ / 32), blk>>>(wv, wvh, wvl, E_, KVH_ * HD_);
        transpose_hilo_kernel<<<dim3(E_ / 32, E_ / 32), blk>>>(wo, woh, wol, E_, E_);
    }

    cudaFuncSetAttribute(gemm_qkv_kernel,
                         cudaFuncAttributeMaxDynamicSharedMemorySize, GSMEM);
    cudaFuncSetAttribute(gemm_bf16x3_kernel,
                         cudaFuncAttributeMaxDynamicSharedMemorySize, GSMEM);

    // Fused QKV projection + RoPE + split + relayout
    gemm_qkv_kernel<<<dim3(NQKV / 128, M_ / 128), 256, GSMEM>>>(
        xhi, xlo, wqh, wql, wkh, wkl, wvh, wvl, bq, bk, bv,
        qbh, qbl, kbh, kbl, vbh, vbl);

    // Flash attention (HMMA split-bf16, Br=128)
    cudaFuncSetAttribute(flash_mma_kernel,
                         cudaFuncAttributeMaxDynamicSharedMemorySize, FSMEM);
    flash_mma_kernel<<<dim3(S_ / 128, H_, B_), 256, FSMEM>>>(
        qbh, qbl, kbh, kbl, vbh, vbl, aohi, aolo);

    // Output projection -> d_out
    gemm_bf16x3_kernel<<<dim3(E_ / 128, M_ / 128), 256, GSMEM>>>(
        aohi, aolo, woh, wol, bo, out, M_, E_, E_);
}

// round 8
// speedup vs baseline: 1.0653x; 1.0653x over previous
#include <cuda_runtime.h>
#include <cuda_bf16.h>
#include <math.h>
#include <cstdint>

#define B_   2
#define S_   2048
#define E_   2048
#define H_   16
#define KVH_ 4
#define HD_  128
#define REP_ 4
#define M_   (B_*S_)     // 4096
#define NQKV 3072        // 2048 Q + 512 K + 512 V

// ---------------------------------------------------------------------------
// Scratch (__device__ globals; no allocations allowed)
// ---------------------------------------------------------------------------
__device__ float g_QKV[M_*NQKV];

__device__ __nv_bfloat16 g_xhi[M_*E_],  g_xlo[M_*E_];
__device__ __nv_bfloat16 g_aohi[M_*E_], g_aolo[M_*E_];
__device__ __nv_bfloat16 g_wqT_hi[E_*E_],        g_wqT_lo[E_*E_];
__device__ __nv_bfloat16 g_wkT_hi[KVH_*HD_*E_],  g_wkT_lo[KVH_*HD_*E_];
__device__ __nv_bfloat16 g_wvT_hi[KVH_*HD_*E_],  g_wvT_lo[KVH_*HD_*E_];
__device__ __nv_bfloat16 g_woT_hi[E_*E_],        g_woT_lo[E_*E_];

// flash operand layouts: Q [B][H][S][HD], K/V [B][KVH][S][HD]
__device__ __nv_bfloat16 g_Qbh[M_*H_*HD_],   g_Qbl[M_*H_*HD_];
__device__ __nv_bfloat16 g_Kbh[M_*KVH_*HD_], g_Kbl[M_*KVH_*HD_];
__device__ __nv_bfloat16 g_Vbh[M_*KVH_*HD_], g_Vbl[M_*KVH_*HD_];

// ---------------------------------------------------------------------------
// PTX helpers (non-'a' ISA only: mma.sync / ldmatrix / cp.async)
// ---------------------------------------------------------------------------
__device__ __forceinline__ uint32_t smem_to_u32(const void* p) {
    uint32_t a;
    asm("{ .reg .u64 t; cvta.to.shared.u64 t, %1; cvt.u32.u64 %0, t; }" : "=r"(a) : "l"(p));
    return a;
}
__device__ __forceinline__ void cp_async16(uint32_t saddr, const void* gptr) {
    asm volatile("cp.async.cg.shared.global [%0], [%1], 16;\n" :: "r"(saddr), "l"(gptr));
}
#define CP_COMMIT() asm volatile("cp.async.commit_group;\n" ::: "memory")
#define CP_WAIT(n)  asm volatile("cp.async.wait_group %0;\n" :: "n"(n) : "memory")

__device__ __forceinline__ void ldmatrix_x4(uint32_t* r, uint32_t addr) {
    asm volatile("ldmatrix.sync.aligned.m8n8.x4.shared.b16 {%0,%1,%2,%3}, [%4];\n"
                 : "=r"(r[0]), "=r"(r[1]), "=r"(r[2]), "=r"(r[3]) : "r"(addr));
}
__device__ __forceinline__ void ldmatrix_x4_trans(uint32_t* r, uint32_t addr) {
    asm volatile("ldmatrix.sync.aligned.m8n8.x4.trans.shared.b16 {%0,%1,%2,%3}, [%4];\n"
                 : "=r"(r[0]), "=r"(r[1]), "=r"(r[2]), "=r"(r[3]) : "r"(addr));
}
__device__ __forceinline__ void ldmatrix_x2(uint32_t* r, uint32_t addr) {
    asm volatile("ldmatrix.sync.aligned.m8n8.x2.shared.b16 {%0,%1}, [%2];\n"
                 : "=r"(r[0]), "=r"(r[1]) : "r"(addr));
}
__device__ __forceinline__ void mma_bf16(float* c, const uint32_t* a, const uint32_t* b) {
    asm volatile(
        "mma.sync.aligned.m16n8k16.row.col.f32.bf16.bf16.f32 "
        "{%0,%1,%2,%3}, {%4,%5,%6,%7}, {%8,%9}, {%0,%1,%2,%3};\n"
        : "+f"(c[0]), "+f"(c[1]), "+f"(c[2]), "+f"(c[3])
        : "r"(a[0]), "r"(a[1]), "r"(a[2]), "r"(a[3]), "r"(b[0]), "r"(b[1]));
}
__device__ __forceinline__ void split2(float a, float b, uint32_t& hi, uint32_t& lo) {
    __nv_bfloat162 h = __floats2bfloat162_rn(a, b);
    __nv_bfloat162 l = __floats2bfloat162_rn(a - __bfloat162float(h.x),
                                             b - __bfloat162float(h.y));
    hi = *(uint32_t*)&h;
    lo = *(uint32_t*)&l;
}

// ---------------------------------------------------------------------------
// Conversion kernels
// ---------------------------------------------------------------------------
__global__ void convert_hilo_kernel(const float* __restrict__ in,
                                    __nv_bfloat16* __restrict__ hi,
                                    __nv_bfloat16* __restrict__ lo, int n4)
{
    int i = blockIdx.x * blockDim.x + threadIdx.x;
    if (i >= n4) return;
    float4 v = ((const float4*)in)[i];
    float a[4] = {v.x, v.y, v.z, v.w};
    __nv_bfloat16 h[4], l[4];
    #pragma unroll
    for (int j = 0; j < 4; j++) {
        h[j] = __float2bfloat16_rn(a[j]);
        l[j] = __float2bfloat16_rn(a[j] - __bfloat162float(h[j]));
    }
    __nv_bfloat162* ph = (__nv_bfloat162*)(hi + 4 * (size_t)i);
    __nv_bfloat162* pl = (__nv_bfloat162*)(lo + 4 * (size_t)i);
    ph[0] = __nv_bfloat162{h[0], h[1]}; ph[1] = __nv_bfloat162{h[2], h[3]};
    pl[0] = __nv_bfloat162{l[0], l[1]}; pl[1] = __nv_bfloat162{l[2], l[3]};
}

// W[K x N] fp32 -> WT_hi/lo[N x K] bf16
__global__ void transpose_hilo_kernel(const float* __restrict__ W,
                                      __nv_bfloat16* __restrict__ Thi,
                                      __nv_bfloat16* __restrict__ Tlo,
                                      int K, int N)
{
    __shared__ float tile[32][33];
    int n0 = blockIdx.x * 32, k0 = blockIdx.y * 32;
    int tx = threadIdx.x, ty = threadIdx.y;
    #pragma unroll
    for (int r = 0; r < 4; r++)
        tile[ty + r * 8][tx] = W[(size_t)(k0 + ty + r * 8) * N + n0 + tx];
    __syncthreads();
    #pragma unroll
    for (int r = 0; r < 4; r++) {
        float v = tile[tx][ty + r * 8];
        __nv_bfloat16 h = __float2bfloat16_rn(v);
        __nv_bfloat16 l = __float2bfloat16_rn(v - __bfloat162float(h));
        size_t o = (size_t)(n0 + ty + r * 8) * K + k0 + tx;
        Thi[o] = h; Tlo[o] = l;
    }
}

// RoPE + hi/lo split; src = QKV buffer (row stride NQKV, col base h*HD)
__global__ void rope_split_kernel(const float* __restrict__ in,
                                  __nv_bfloat16* __restrict__ outh,
                                  __nv_bfloat16* __restrict__ outl,
                                  int nh, float scale)
{
    int idx = blockIdx.x * blockDim.x + threadIdx.x;
    int total = B_ * S_ * nh * (HD_ / 2);
    if (idx >= total) return;
    int d2 = idx & 63;
    int h  = (idx >> 6) % nh;
    int s  = (idx / (64 * nh)) % S_;
    int b  = idx / (64 * nh * S_);
    float p    = powf(100000.0f, (float)(2 * d2));   // inf for 2*d2 >= 8
    float freq = 1.0f / p;                           // 0 when p == inf
    float ang  = (float)s * freq;
    float sn, cs;
    sincosf(ang, &sn, &cs);
    size_t src = (size_t)(b * S_ + s) * NQKV + h * HD_ + 2 * d2;
    float tr = in[src], ti = in[src + 1];
    float o0 = (tr * cs - ti * sn) * scale;
    float o1 = (tr * sn + ti * cs) * scale;
    uint32_t hi, lo;
    split2(o0, o1, hi, lo);
    size_t dst = ((size_t)(b * nh + h) * S_ + s) * HD_ + 2 * d2;
    *(uint32_t*)(outh + dst) = hi;
    *(uint32_t*)(outl + dst) = lo;
}

// V: hi/lo split + relayout from QKV buffer
__global__ void v_split_kernel(const float* __restrict__ in,
                               __nv_bfloat16* __restrict__ outh,
                               __nv_bfloat16* __restrict__ outl)
{
    int idx = blockIdx.x * blockDim.x + threadIdx.x;
    int total = B_ * S_ * KVH_ * (HD_ / 2);
    if (idx >= total) return;
    int d2 = idx & 63;
    int g  = (idx >> 6) % KVH_;
    int s  = (idx / (64 * KVH_)) % S_;
    int b  = idx / (64 * KVH_ * S_);
    size_t src = (size_t)(b * S_ + s) * NQKV + g * HD_ + 2 * d2;
    float2 v = *(const float2*)(in + src);
    uint32_t hi, lo;
    split2(v.x, v.y, hi, lo);
    size_t dst = ((size_t)(b * KVH_ + g) * S_ + s) * HD_ + 2 * d2;
    *(uint32_t*)(outh + dst) = hi;
    *(uint32_t*)(outl + dst) = lo;
}

// ---------------------------------------------------------------------------
// Split-bf16 HMMA GEMM mainloop: 128x128 tile, K chunks of 32, 2 stages,
// 80 KB smem -> 2 CTAs/SM (16 warps) for latency hiding.
// ---------------------------------------------------------------------------
#define GBK      32
#define GROWB    80                    // 64B data + 16 pad
#define GARR     (128 * GROWB)         // 10240
#define GSTAGE   (4 * GARR)            // 40960
#define GSTAGES  2
#define GSMEM    (GSTAGES * GSTAGE)    // 81920 -> 2 CTAs/SM

__device__ __forceinline__ void gemm_mainloop(
    const __nv_bfloat16* __restrict__ Ahi, const __nv_bfloat16* __restrict__ Alo,
    const __nv_bfloat16* __restrict__ Bhi, const __nv_bfloat16* __restrict__ Blo,
    int rowA0, int rowB0, int K, uint32_t sb, int tid, float acc[4][4][4])
{
    const int wid  = tid >> 5;
    const int lane = tid & 31;
    const int warp_m = wid >> 2;
    const int warp_n = wid & 3;
    const int nchunks = K / GBK;

    const int a_lr = lane & 15;
    const int a_kc = (lane >> 4) * 8;
    const int b_lr = lane & 7;
    const int b_kc = ((lane >> 3) & 3) * 8;

    // per-thread load mapping: 1 x 16B per array per stage (256 thr * 16B = 4KB... )
    // stage array = 128 rows x 64B data: 512 cp16 / 256 threads = 2 per thread
    const int lr0 = tid >> 2,            lc0 = tid & 3;
    const int lr1 = (tid + 256) >> 2,    lc1 = tid & 3;   // rows 64..127

    auto load_stage = [&](int chunk, int stage) {
        const int k0 = chunk * GBK;
        uint32_t s = sb + stage * GSTAGE;
        const __nv_bfloat16* ptrs[4] = {Ahi, Alo, Bhi, Blo};
        const int rows[4] = {rowA0, rowA0, rowB0, rowB0};
        #pragma unroll
        for (int arr = 0; arr < 4; arr++) {
            cp_async16(s + arr * GARR + lr0 * GROWB + lc0 * 16,
                       ptrs[arr] + (size_t)(rows[arr] + lr0) * K + k0 + lc0 * 8);
            cp_async16(s + arr * GARR + lr1 * GROWB + lc1 * 16,
                       ptrs[arr] + (size_t)(rows[arr] + lr1) * K + k0 + lc1 * 8);
        }
    };

    #pragma unroll
    for (int s = 0; s < GSTAGES; s++) { load_stage(s, s); CP_COMMIT(); }

    for (int i = 0; i < nchunks; i++) {
        CP_WAIT(GSTAGES - 1);
        __syncthreads();

        const int stage = i % GSTAGES;
        const uint32_t sAhi = sb + stage * GSTAGE;
        const uint32_t sAlo = sAhi + GARR;
        const uint32_t sBhi = sAlo + GARR;
        const uint32_t sBlo = sBhi + GARR;

        #pragma unroll
        for (int ks = 0; ks < 2; ks++) {
            const int kb = ks * 32;
            uint32_t ah[4][4], al[4][4], bh[4][2], bl[4][2];
            #pragma unroll
            for (int mt = 0; mt < 4; mt++) {
                uint32_t aoff = (uint32_t)(warp_m * 64 + mt * 16 + a_lr) * GROWB + a_kc * 2 + kb;
                ldmatrix_x4(ah[mt], sAhi + aoff);
                ldmatrix_x4(al[mt], sAlo + aoff);
            }
            #pragma unroll
            for (int nt = 0; nt < 4; nt++) {
                uint32_t boff = (uint32_t)(warp_n * 32 + nt * 8 + b_lr) * GROWB + b_kc * 2 + kb;
                ldmatrix_x2(bh[nt], sBhi + boff);
                ldmatrix_x2(bl[nt], sBlo + boff);
            }
            #pragma unroll
            for (int mt = 0; mt < 4; mt++)
                #pragma unroll
                for (int nt = 0; nt < 4; nt++) {
                    mma_bf16(acc[mt][nt], ah[mt], bh[nt]);
                    mma_bf16(acc[mt][nt], ah[mt], bl[nt]);
                    mma_bf16(acc[mt][nt], al[mt], bh[nt]);
                }
        }
        __syncthreads();
        if (i + GSTAGES < nchunks) load_stage(i + GSTAGES, stage);
        CP_COMMIT();
    }
}

// Generic GEMM (O projection): C[M,N] row stride N
__global__ void __launch_bounds__(256, 2)
gemm_bf16x3_kernel(const __nv_bfloat16* __restrict__ Ahi,
                   const __nv_bfloat16* __restrict__ Alo,
                   const __nv_bfloat16* __restrict__ Bhi,
                   const __nv_bfloat16* __restrict__ Blo,
                   const float* __restrict__ bias,
                   float* __restrict__ C,
                   int M, int N, int K)
{
    extern __shared__ char smem[];
    const uint32_t sb = smem_to_u32(smem);
    const int tid  = threadIdx.x;
    const int wid  = tid >> 5;
    const int lane = tid & 31;
    const int rowA0 = blockIdx.y * 128;
    const int rowB0 = blockIdx.x * 128;

    float acc[4][4][4];
    #pragma unroll
    for (int i = 0; i < 4; i++)
        #pragma unroll
        for (int j = 0; j < 4; j++)
            #pragma unroll
            for (int k = 0; k < 4; k++) acc[i][j][k] = 0.0f;

    gemm_mainloop(Ahi, Alo, Bhi, Blo, rowA0, rowB0, K, sb, tid, acc);

    const int warp_m = wid >> 2, warp_n = wid & 3;
    #pragma unroll
    for (int mt = 0; mt < 4; mt++)
        #pragma unroll
        for (int nt = 0; nt < 4; nt++) {
            int row = rowA0 + warp_m * 64 + mt * 16 + (lane >> 2);
            int col = rowB0 + warp_n * 32 + nt * 8 + (lane & 3) * 2;
            float2 b01 = *(const float2*)&bias[col];
            float2 o0 = {acc[mt][nt][0] + b01.x, acc[mt][nt][1] + b01.y};
            float2 o1 = {acc[mt][nt][2] + b01.x, acc[mt][nt][3] + b01.y};
            *(float2*)&C[(size_t)row * N + col]       = o0;
            *(float2*)&C[(size_t)(row + 8) * N + col] = o1;
        }
}

// Fused QKV projection: writes into QKV buffer [M][3072]
__global__ void __launch_bounds__(256, 2)
gemm_qkv_kernel(const __nv_bfloat16* __restrict__ xhi,
                const __nv_bfloat16* __restrict__ xlo,
                const __nv_bfloat16* __restrict__ wqh, const __nv_bfloat16* __restrict__ wql,
                const __nv_bfloat16* __restrict__ wkh, const __nv_bfloat16* __restrict__ wkl,
                const __nv_bfloat16* __restrict__ wvh, const __nv_bfloat16* __restrict__ wvl,
                const float* __restrict__ bq, const float* __restrict__ bk,
                const float* __restrict__ bv,
                float* __restrict__ C)
{
    extern __shared__ char smem[];
    const uint32_t sb = smem_to_u32(smem);
    const int tid  = threadIdx.x;
    const int wid  = tid >> 5;
    const int lane = tid & 31;
    const int cCol = blockIdx.x;         // 0..23
    const int rowA0 = blockIdx.y * 128;

    const __nv_bfloat16 *Bh, *Bl;
    const float* bias;
    int rowB0;
    if (cCol < 16)      { Bh = wqh; Bl = wql; bias = bq; rowB0 = cCol * 128; }
    else if (cCol < 20) { Bh = wkh; Bl = wkl; bias = bk; rowB0 = (cCol - 16) * 128; }
    else                { Bh = wvh; Bl = wvl; bias = bv; rowB0 = (cCol - 20) * 128; }

    float acc[4][4][4];
    #pragma unroll
    for (int i = 0; i < 4; i++)
        #pragma unroll
        for (int j = 0; j < 4; j++)
            #pragma unroll
            for (int k = 0; k < 4; k++) acc[i][j][k] = 0.0f;

    gemm_mainloop(xhi, xlo, Bh, Bl, rowA0, rowB0, E_, sb, tid, acc);

    const int warp_m = wid >> 2, warp_n = wid & 3;
    #pragma unroll
    for (int mt = 0; mt < 4; mt++)
        #pragma unroll
        for (int nt = 0; nt < 4; nt++) {
            int row  = rowA0 + warp_m * 64 + mt * 16 + (lane >> 2);
            int bcol = rowB0 + warp_n * 32 + nt * 8 + (lane & 3) * 2;        // within bias
            int col  = cCol * 128 + warp_n * 32 + nt * 8 + (lane & 3) * 2;   // within QKV
            float2 b01 = *(const float2*)&bias[bcol];
            float2 o0 = {acc[mt][nt][0] + b01.x, acc[mt][nt][1] + b01.y};
            float2 o1 = {acc[mt][nt][2] + b01.x, acc[mt][nt][3] + b01.y};
            *(float2*)&C[(size_t)row * NQKV + col]       = o0;
            *(float2*)&C[(size_t)(row + 8) * NQKV + col] = o1;
        }
}

// ---------------------------------------------------------------------------
// Flash attention, split-bf16 HMMA. Br=128, Bc=64, HD=128, 8 warps.
// ---------------------------------------------------------------------------
#define FROWB  272
#define QARR   (128 * FROWB)        // 34816
#define KARR   (64 * FROWB)         // 17408
#define FSTG   (4 * KARR)           // 69632 (Kh,Kl,Vh,Vl)
#define FSMEM  (2 * QARR + 2 * FSTG)  // 208896

__global__ void __launch_bounds__(256, 1)
flash_mma_kernel(const __nv_bfloat16* __restrict__ Qh, const __nv_bfloat16* __restrict__ Ql,
                 const __nv_bfloat16* __restrict__ Kh, const __nv_bfloat16* __restrict__ Kl,
                 const __nv_bfloat16* __restrict__ Vh, const __nv_bfloat16* __restrict__ Vl,
                 __nv_bfloat16* __restrict__ Ohi, __nv_bfloat16* __restrict__ Olo)
{
    extern __shared__ char smem[];
    const uint32_t sb = smem_to_u32(smem);
    const int tid  = threadIdx.x;
    const int lane = tid & 31;
    const int warp = tid >> 5;
    const int qt = (int)gridDim.x - 1 - (int)blockIdx.x;   // heavy tiles first
    const int h = blockIdx.y, b = blockIdx.z;
    const int g  = h >> 2;
    const int q0 = qt * 128;
    const int nkv = 2 * qt + 2;

    const uint32_t sQh = sb, sQl = sb + QARR;
    const uint32_t sKV0 = sb + 2 * QARR;

    const size_t qbase  = ((size_t)(b * H_ + h) * S_ + q0) * HD_;
    const size_t kvbase = ((size_t)(b * KVH_ + g) * S_) * HD_;

    const uint32_t q_off = (uint32_t)(lane & 15) * FROWB + (lane >> 4) * 16;
    const uint32_t k_off = (uint32_t)((lane & 7) | ((lane >> 1) & 8)) * FROWB + ((lane >> 3) & 1) * 16;

    // -- prologue: Q tile (128 rows) + KV stage 0 --
    #pragma unroll
    for (int t = 0; t < 8; t++) {
        int u = t * 256 + tid;                  // 0..2047
        int r = u >> 4, cb = (u & 15) * 16, ce = (u & 15) * 8;
        cp_async16(sQh + r * FROWB + cb, Qh + qbase + (size_t)r * HD_ + ce);
        cp_async16(sQl + r * FROWB + cb, Ql + qbase + (size_t)r * HD_ + ce);
    }
    auto load_kv = [&](int kt, int buf) {
        uint32_t s = sKV0 + buf * FSTG;
        const size_t base = kvbase + (size_t)kt * 64 * HD_;
        #pragma unroll
        for (int t = 0; t < 4; t++) {
            int u = t * 256 + tid;              // 0..1023
            int r = u >> 4, cb = (u & 15) * 16, ce = (u & 15) * 8;
            size_t go = base + (size_t)r * HD_ + ce;
            uint32_t so = r * FROWB + cb;
            cp_async16(s + so,            Kh + go);
            cp_async16(s + KARR + so,     Kl + go);
            cp_async16(s + 2 * KARR + so, Vh + go);
            cp_async16(s + 3 * KARR + so, Vl + go);
        }
    };
    load_kv(0, 0);
    CP_COMMIT();

    float oacc[16][4];
    #pragma unroll
    for (int i = 0; i < 16; i++)
        #pragma unroll
        for (int j = 0; j < 4; j++) oacc[i][j] = 0.0f;
    float m0 = -INFINITY, m1 = -INFINITY, l0 = 0.0f, l1 = 0.0f;

    for (int kt = 0; kt < nkv; kt++) {
        __syncthreads();
        if (kt + 1 < nkv) { load_kv(kt + 1, (kt + 1) & 1); CP_COMMIT(); CP_WAIT(1); }
        else              { CP_WAIT(0); }
        __syncthreads();

        const uint32_t st  = sKV0 + (kt & 1) * FSTG;
        const uint32_t sKh = st, sKl = st + KARR, sVh = st + 2 * KARR, sVl = st + 3 * KARR;

        // ---- S = Q K^T ----
        float sacc[8][4];
        #pragma unroll
        for (int i = 0; i < 8; i++)
            #pragma unroll
            for (int j = 0; j < 4; j++) sacc[i][j] = 0.0f;

        #pragma unroll
        for (int kk = 0; kk < 8; kk++) {
            const uint32_t kb = kk * 32;
            uint32_t qh[4], ql[4];
            ldmatrix_x4(qh, sQh + (uint32_t)warp * 16 * FROWB + q_off + kb);
            ldmatrix_x4(ql, sQl + (uint32_t)warp * 16 * FROWB + q_off + kb);
            #pragma unroll
            for (int np = 0; np < 4; np++) {
                uint32_t kh[4], kl[4];
                ldmatrix_x4(kh, sKh + (uint32_t)np * 16 * FROWB + k_off + kb);
                ldmatrix_x4(kl, sKl + (uint32_t)np * 16 * FROWB + k_off + kb);
                mma_bf16(sacc[2*np],   qh, &kh[0]);
                mma_bf16(sacc[2*np],   qh, &kl[0]);
                mma_bf16(sacc[2*np],   ql, &kh[0]);
                mma_bf16(sacc[2*np+1], qh, &kh[2]);
                mma_bf16(sacc[2*np+1], qh, &kl[2]);
                mma_bf16(sacc[2*np+1], ql, &kh[2]);
            }
        }

        // ---- causal mask (diagonal region spans kv chunks 2qt, 2qt+1) ----
        if (kt >= 2 * qt) {
            const int rg0 = q0 + warp * 16 + (lane >> 2);
            const int cg0 = kt * 64 + (lane & 3) * 2;
            #pragma unroll
            for (int nt = 0; nt < 8; nt++)
                #pragma unroll
                for (int j = 0; j < 4; j++) {
                    int col = cg0 + nt * 8 + (j & 1);
                    int row = rg0 + (j >> 1) * 8;
                    if (col > row) sacc[nt][j] = -INFINITY;
                }
        }

        // ---- online softmax ----
        float mx0 = -INFINITY, mx1 = -INFINITY;
        #pragma unroll
        for (int nt = 0; nt < 8; nt++) {
            mx0 = fmaxf(mx0, fmaxf(sacc[nt][0], sacc[nt][1]));
            mx1 = fmaxf(mx1, fmaxf(sacc[nt][2], sacc[nt][3]));
        }
        mx0 = fmaxf(mx0, __shfl_xor_sync(0xFFFFFFFF, mx0, 1));
        mx0 = fmaxf(mx0, __shfl_xor_sync(0xFFFFFFFF, mx0, 2));
        mx1 = fmaxf(mx1, __shfl_xor_sync(0xFFFFFFFF, mx1, 1));
        mx1 = fmaxf(mx1, __shfl_xor_sync(0xFFFFFFFF, mx1, 2));
        float mn0 = fmaxf(m0, mx0), mn1 = fmaxf(m1, mx1);
        float al0 = __expf(m0 - mn0), al1 = __expf(m1 - mn1);
        m0 = mn0; m1 = mn1;

        float ps0 = 0.0f, ps1 = 0.0f;
        #pragma unroll
        for (int nt = 0; nt < 8; nt++) {
            float p0 = __expf(sacc[nt][0] - mn0);
            float p1 = __expf(sacc[nt][1] - mn0);
            float p2 = __expf(sacc[nt][2] - mn1);
            float p3 = __expf(sacc[nt][3] - mn1);
            sacc[nt][0] = p0; sacc[nt][1] = p1; sacc[nt][2] = p2; sacc[nt][3] = p3;
            ps0 += p0 + p1; ps1 += p2 + p3;
        }
        ps0 += __shfl_xor_sync(0xFFFFFFFF, ps0, 1);
        ps0 += __shfl_xor_sync(0xFFFFFFFF, ps0, 2);
        ps1 += __shfl_xor_sync(0xFFFFFFFF, ps1, 1);
        ps1 += __shfl_xor_sync(0xFFFFFFFF, ps1, 2);
        l0 = l0 * al0 + ps0;
        l1 = l1 * al1 + ps1;

        #pragma unroll
        for (int i = 0; i < 16; i++) {
            oacc[i][0] *= al0; oacc[i][1] *= al0;
            oacc[i][2] *= al1; oacc[i][3] *= al1;
        }

        // ---- O += P V ----
        #pragma unroll
        for (int tk = 0; tk < 4; tk++) {
            uint32_t ah[4], al_[4];
            split2(sacc[2*tk][0],   sacc[2*tk][1],   ah[0], al_[0]);
            split2(sacc[2*tk][2],   sacc[2*tk][3],   ah[1], al_[1]);
            split2(sacc[2*tk+1][0], sacc[2*tk+1][1], ah[2], al_[2]);
            split2(sacc[2*tk+1][2], sacc[2*tk+1][3], ah[3], al_[3]);
            #pragma unroll
            for (int dp = 0; dp < 8; dp++) {
                uint32_t vh[4], vl[4];
                const uint32_t vo = (uint32_t)tk * 16 * FROWB + q_off + dp * 32;
                ldmatrix_x4_trans(vh, sVh + vo);
                ldmatrix_x4_trans(vl, sVl + vo);
                mma_bf16(oacc[2*dp],   ah,  &vh[0]);
                mma_bf16(oacc[2*dp],   ah,  &vl[0]);
                mma_bf16(oacc[2*dp],   al_, &vh[0]);
                mma_bf16(oacc[2*dp+1], ah,  &vh[2]);
                mma_bf16(oacc[2*dp+1], ah,  &vl[2]);
                mma_bf16(oacc[2*dp+1], al_, &vh[2]);
            }
        }
    }

    // ---- epilogue: O / l -> hi/lo bf16 at [b][s][h*HD] ----
    const float il0 = 1.0f / l0, il1 = 1.0f / l1;
    const int r0 = q0 + warp * 16 + (lane >> 2);
    const int c0 = h * HD_ + (lane & 3) * 2;
    #pragma unroll
    for (int nt = 0; nt < 16; nt++) {
        float o0 = oacc[nt][0] * il0, o1 = oacc[nt][1] * il0;
        float o2 = oacc[nt][2] * il1, o3 = oacc[nt][3] * il1;
        uint32_t h0, l0r, h1, l1r;
        split2(o0, o1, h0, l0r);
        split2(o2, o3, h1, l1r);
        size_t i0 = (size_t)(b * S_ + r0)     * E_ + c0 + nt * 8;
        size_t i1 = (size_t)(b * S_ + r0 + 8) * E_ + c0 + nt * 8;
        *(uint32_t*)(Ohi + i0) = h0; *(uint32_t*)(Olo + i0) = l0r;
        *(uint32_t*)(Ohi + i1) = h1; *(uint32_t*)(Olo + i1) = l1r;
    }
}

// ---------------------------------------------------------------------------
extern "C" void kernel_launch(void* const* d_in, const int* in_sizes, int n_in,
                              void* d_out, int out_size)
{
    const float* x  = (const float*)d_in[0];
    const float* wq = (const float*)d_in[1];
    const float* bq = (const float*)d_in[2];
    const float* wk = (const float*)d_in[3];
    const float* bk = (const float*)d_in[4];
    const float* wv = (const float*)d_in[5];
    const float* bv = (const float*)d_in[6];
    const float* wo = (const float*)d_in[7];
    const float* bo = (const float*)d_in[8];
    float* out = (float*)d_out;

    float* QKVp;
    cudaGetSymbolAddress((void**)&QKVp, g_QKV);
    __nv_bfloat16 *xhi, *xlo, *aohi, *aolo;
    __nv_bfloat16 *wqh, *wql, *wkh, *wkl, *wvh, *wvl, *woh, *wol;
    __nv_bfloat16 *qbh, *qbl, *kbh, *kbl, *vbh, *vbl;
    cudaGetSymbolAddress((void**)&xhi,  g_xhi);
    cudaGetSymbolAddress((void**)&xlo,  g_xlo);
    cudaGetSymbolAddress((void**)&aohi, g_aohi);
    cudaGetSymbolAddress((void**)&aolo, g_aolo);
    cudaGetSymbolAddress((void**)&wqh, g_wqT_hi);
    cudaGetSymbolAddress((void**)&wql, g_wqT_lo);
    cudaGetSymbolAddress((void**)&wkh, g_wkT_hi);
    cudaGetSymbolAddress((void**)&wkl, g_wkT_lo);
    cudaGetSymbolAddress((void**)&wvh, g_wvT_hi);
    cudaGetSymbolAddress((void**)&wvl, g_wvT_lo);
    cudaGetSymbolAddress((void**)&woh, g_woT_hi);
    cudaGetSymbolAddress((void**)&wol, g_woT_lo);
    cudaGetSymbolAddress((void**)&qbh, g_Qbh);
    cudaGetSymbolAddress((void**)&qbl, g_Qbl);
    cudaGetSymbolAddress((void**)&kbh, g_Kbh);
    cudaGetSymbolAddress((void**)&kbl, g_Kbl);
    cudaGetSymbolAddress((void**)&vbh, g_Vbh);
    cudaGetSymbolAddress((void**)&vbl, g_Vbl);

    // conversions
    {
        int n4 = M_ * E_ / 4;
        convert_hilo_kernel<<<(n4 + 255) / 256, 256>>>(x, xhi, xlo, n4);
        dim3 blk(32, 8);
        transpose_hilo_kernel<<<dim3(E_ / 32, E_ / 32), blk>>>(wq, wqh, wql, E_, E_);
        transpose_hilo_kernel<<<dim3((KVH_ * HD_) / 32, E_ / 32), blk>>>(wk, wkh, wkl, E_, KVH_ * HD_);
        transpose_hilo_kernel<<<dim3((KVH_ * HD_) / 32, E_ / 32), blk>>>(wv, wvh, wvl, E_, KVH_ * HD_);
        transpose_hilo_kernel<<<dim3(E_ / 32, E_ / 32), blk>>>(wo, woh, wol, E_, E_);
    }

    cudaFuncSetAttribute(gemm_qkv_kernel,
                         cudaFuncAttributeMaxDynamicSharedMemorySize, GSMEM);
    cudaFuncSetAttribute(gemm_bf16x3_kernel,
                         cudaFuncAttributeMaxDynamicSharedMemorySize, GSMEM);

    // Fused QKV projection (N = 3072)
    gemm_qkv_kernel<<<dim3(NQKV / 128, M_ / 128), 256, GSMEM>>>(
        xhi, xlo, wqh, wql, wkh, wkl, wvh, wvl, bq, bk, bv, QKVp);

    // RoPE + split + relayout (reads QKV buffer)
    {
        int totq = B_ * S_ * H_ * (HD_ / 2);
        int totk = B_ * S_ * KVH_ * (HD_ / 2);
        float qscale = 1.0f / sqrtf((float)HD_);
        rope_split_kernel<<<(totq + 255) / 256, 256>>>(QKVp, qbh, qbl, H_, qscale);
        rope_split_kernel<<<(totk + 255) / 256, 256>>>(QKVp + 2048, kbh, kbl, KVH_, 1.0f);
        v_split_kernel<<<(totk + 255) / 256, 256>>>(QKVp + 2560, vbh, vbl);
    }

    // Flash attention (HMMA split-bf16, Br=128)
    cudaFuncSetAttribute(flash_mma_kernel,
                         cudaFuncAttributeMaxDynamicSharedMemorySize, FSMEM);
    flash_mma_kernel<<<dim3(S_ / 128, H_, B_), 256, FSMEM>>>(
        qbh, qbl, kbh, kbl, vbh, vbl, aohi, aolo);

    // Output projection -> d_out
    gemm_bf16x3_kernel<<<dim3(E_ / 128, M_ / 128), 256, GSMEM>>>(
        aohi, aolo, woh, wol, bo, out, M_, E_, E_);
}

// round 9
// speedup vs baseline: 1.0886x; 1.0219x over previous
#include <cuda_runtime.h>
#include <cuda_bf16.h>
#include <math.h>
#include <cstdint>

#define B_   2
#define S_   2048
#define E_   2048
#define H_   16
#define KVH_ 4
#define HD_  128
#define REP_ 4
#define M_   (B_*S_)     // 4096
#define NQKV 3072        // 2048 Q + 512 K + 512 V

// ---------------------------------------------------------------------------
// Scratch (__device__ globals; no allocations allowed)
// ---------------------------------------------------------------------------
__device__ float g_QKV[M_*NQKV];

__device__ __nv_bfloat16 g_xhi[M_*E_],  g_xlo[M_*E_];
__device__ __nv_bfloat16 g_aohi[M_*E_], g_aolo[M_*E_];
__device__ __nv_bfloat16 g_wqT_hi[E_*E_],        g_wqT_lo[E_*E_];
__device__ __nv_bfloat16 g_wkT_hi[KVH_*HD_*E_],  g_wkT_lo[KVH_*HD_*E_];
__device__ __nv_bfloat16 g_wvT_hi[KVH_*HD_*E_],  g_wvT_lo[KVH_*HD_*E_];
__device__ __nv_bfloat16 g_woT_hi[E_*E_],        g_woT_lo[E_*E_];

// flash operand layouts: Q [B][H][S][HD], K/V [B][KVH][S][HD]
__device__ __nv_bfloat16 g_Qbh[M_*H_*HD_],   g_Qbl[M_*H_*HD_];
__device__ __nv_bfloat16 g_Kbh[M_*KVH_*HD_], g_Kbl[M_*KVH_*HD_];
__device__ __nv_bfloat16 g_Vbh[M_*KVH_*HD_], g_Vbl[M_*KVH_*HD_];

// ---------------------------------------------------------------------------
// PTX helpers (non-'a' ISA only: mma.sync / ldmatrix / cp.async)
// ---------------------------------------------------------------------------
__device__ __forceinline__ uint32_t smem_to_u32(const void* p) {
    uint32_t a;
    asm("{ .reg .u64 t; cvta.to.shared.u64 t, %1; cvt.u32.u64 %0, t; }" : "=r"(a) : "l"(p));
    return a;
}
__device__ __forceinline__ void cp_async16(uint32_t saddr, const void* gptr) {
    asm volatile("cp.async.cg.shared.global [%0], [%1], 16;\n" :: "r"(saddr), "l"(gptr));
}
#define CP_COMMIT() asm volatile("cp.async.commit_group;\n" ::: "memory")
#define CP_WAIT(n)  asm volatile("cp.async.wait_group %0;\n" :: "n"(n) : "memory")

__device__ __forceinline__ void ldmatrix_x4(uint32_t* r, uint32_t addr) {
    asm volatile("ldmatrix.sync.aligned.m8n8.x4.shared.b16 {%0,%1,%2,%3}, [%4];\n"
                 : "=r"(r[0]), "=r"(r[1]), "=r"(r[2]), "=r"(r[3]) : "r"(addr));
}
__device__ __forceinline__ void ldmatrix_x4_trans(uint32_t* r, uint32_t addr) {
    asm volatile("ldmatrix.sync.aligned.m8n8.x4.trans.shared.b16 {%0,%1,%2,%3}, [%4];\n"
                 : "=r"(r[0]), "=r"(r[1]), "=r"(r[2]), "=r"(r[3]) : "r"(addr));
}
__device__ __forceinline__ void ldmatrix_x2(uint32_t* r, uint32_t addr) {
    asm volatile("ldmatrix.sync.aligned.m8n8.x2.shared.b16 {%0,%1}, [%2];\n"
                 : "=r"(r[0]), "=r"(r[1]) : "r"(addr));
}
__device__ __forceinline__ void mma_bf16(float* c, const uint32_t* a, const uint32_t* b) {
    asm volatile(
        "mma.sync.aligned.m16n8k16.row.col.f32.bf16.bf16.f32 "
        "{%0,%1,%2,%3}, {%4,%5,%6,%7}, {%8,%9}, {%0,%1,%2,%3};\n"
        : "+f"(c[0]), "+f"(c[1]), "+f"(c[2]), "+f"(c[3])
        : "r"(a[0]), "r"(a[1]), "r"(a[2]), "r"(a[3]), "r"(b[0]), "r"(b[1]));
}
__device__ __forceinline__ void split2(float a, float b, uint32_t& hi, uint32_t& lo) {
    __nv_bfloat162 h = __floats2bfloat162_rn(a, b);
    __nv_bfloat162 l = __floats2bfloat162_rn(a - __bfloat162float(h.x),
                                             b - __bfloat162float(h.y));
    hi = *(uint32_t*)&h;
    lo = *(uint32_t*)&l;
}

// ---------------------------------------------------------------------------
// Conversion kernels
// ---------------------------------------------------------------------------
__global__ void convert_hilo_kernel(const float* __restrict__ in,
                                    __nv_bfloat16* __restrict__ hi,
                                    __nv_bfloat16* __restrict__ lo, int n4)
{
    int i = blockIdx.x * blockDim.x + threadIdx.x;
    if (i >= n4) return;
    float4 v = ((const float4*)in)[i];
    float a[4] = {v.x, v.y, v.z, v.w};
    __nv_bfloat16 h[4], l[4];
    #pragma unroll
    for (int j = 0; j < 4; j++) {
        h[j] = __float2bfloat16_rn(a[j]);
        l[j] = __float2bfloat16_rn(a[j] - __bfloat162float(h[j]));
    }
    __nv_bfloat162* ph = (__nv_bfloat162*)(hi + 4 * (size_t)i);
    __nv_bfloat162* pl = (__nv_bfloat162*)(lo + 4 * (size_t)i);
    ph[0] = __nv_bfloat162{h[0], h[1]}; ph[1] = __nv_bfloat162{h[2], h[3]};
    pl[0] = __nv_bfloat162{l[0], l[1]}; pl[1] = __nv_bfloat162{l[2], l[3]};
}

// W[K x N] fp32 -> WT_hi/lo[N x K] bf16
__global__ void transpose_hilo_kernel(const float* __restrict__ W,
                                      __nv_bfloat16* __restrict__ Thi,
                                      __nv_bfloat16* __restrict__ Tlo,
                                      int K, int N)
{
    __shared__ float tile[32][33];
    int n0 = blockIdx.x * 32, k0 = blockIdx.y * 32;
    int tx = threadIdx.x, ty = threadIdx.y;
    #pragma unroll
    for (int r = 0; r < 4; r++)
        tile[ty + r * 8][tx] = W[(size_t)(k0 + ty + r * 8) * N + n0 + tx];
    __syncthreads();
    #pragma unroll
    for (int r = 0; r < 4; r++) {
        float v = tile[tx][ty + r * 8];
        __nv_bfloat16 h = __float2bfloat16_rn(v);
        __nv_bfloat16 l = __float2bfloat16_rn(v - __bfloat162float(h));
        size_t o = (size_t)(n0 + ty + r * 8) * K + k0 + tx;
        Thi[o] = h; Tlo[o] = l;
    }
}

// RoPE + hi/lo split; src = QKV buffer (row stride NQKV, col base h*HD)
__global__ void rope_split_kernel(const float* __restrict__ in,
                                  __nv_bfloat16* __restrict__ outh,
                                  __nv_bfloat16* __restrict__ outl,
                                  int nh, float scale)
{
    int idx = blockIdx.x * blockDim.x + threadIdx.x;
    int total = B_ * S_ * nh * (HD_ / 2);
    if (idx >= total) return;
    int d2 = idx & 63;
    int h  = (idx >> 6) % nh;
    int s  = (idx / (64 * nh)) % S_;
    int b  = idx / (64 * nh * S_);
    float p    = powf(100000.0f, (float)(2 * d2));   // inf for 2*d2 >= 8
    float freq = 1.0f / p;                           // 0 when p == inf
    float ang  = (float)s * freq;
    float sn, cs;
    sincosf(ang, &sn, &cs);
    size_t src = (size_t)(b * S_ + s) * NQKV + h * HD_ + 2 * d2;
    float tr = in[src], ti = in[src + 1];
    float o0 = (tr * cs - ti * sn) * scale;
    float o1 = (tr * sn + ti * cs) * scale;
    uint32_t hi, lo;
    split2(o0, o1, hi, lo);
    size_t dst = ((size_t)(b * nh + h) * S_ + s) * HD_ + 2 * d2;
    *(uint32_t*)(outh + dst) = hi;
    *(uint32_t*)(outl + dst) = lo;
}

// V: hi/lo split + relayout from QKV buffer
__global__ void v_split_kernel(const float* __restrict__ in,
                               __nv_bfloat16* __restrict__ outh,
                               __nv_bfloat16* __restrict__ outl)
{
    int idx = blockIdx.x * blockDim.x + threadIdx.x;
    int total = B_ * S_ * KVH_ * (HD_ / 2);
    if (idx >= total) return;
    int d2 = idx & 63;
    int g  = (idx >> 6) % KVH_;
    int s  = (idx / (64 * KVH_)) % S_;
    int b  = idx / (64 * KVH_ * S_);
    size_t src = (size_t)(b * S_ + s) * NQKV + g * HD_ + 2 * d2;
    float2 v = *(const float2*)(in + src);
    uint32_t hi, lo;
    split2(v.x, v.y, hi, lo);
    size_t dst = ((size_t)(b * KVH_ + g) * S_ + s) * HD_ + 2 * d2;
    *(uint32_t*)(outh + dst) = hi;
    *(uint32_t*)(outl + dst) = lo;
}

// ---------------------------------------------------------------------------
// Split-bf16 HMMA GEMM mainloop: 128x128 tile, K chunks of 64, 3 stages,
// register-level double-buffered fragments (LDSM of ks+1 before MMAs of ks).
// ---------------------------------------------------------------------------
#define GBK      64
#define GROWB    144                   // 128B data + 16 pad
#define GARR     (128 * GROWB)         // 18432
#define GSTAGE   (4 * GARR)            // 73728
#define GSTAGES  3
#define GSMEM    (GSTAGES * GSTAGE)    // 221184

__device__ __forceinline__ void gemm_mainloop(
    const __nv_bfloat16* __restrict__ Ahi, const __nv_bfloat16* __restrict__ Alo,
    const __nv_bfloat16* __restrict__ Bhi, const __nv_bfloat16* __restrict__ Blo,
    int rowA0, int rowB0, int K, uint32_t sb, int tid, float acc[4][4][4])
{
    const int wid  = tid >> 5;
    const int lane = tid & 31;
    const int warp_m = wid >> 2;
    const int warp_n = wid & 3;
    const int nchunks = K / GBK;

    const int a_lr = lane & 15;
    const int a_kc = (lane >> 4) * 8;
    const int b_lr = lane & 7;
    const int b_kc = ((lane >> 3) & 3) * 8;

    auto load_stage = [&](int chunk, int stage) {
        const int k0 = chunk * GBK;
        uint32_t s = sb + stage * GSTAGE;
        const __nv_bfloat16* ptrs[4] = {Ahi, Alo, Bhi, Blo};
        const int rows[4] = {rowA0, rowA0, rowB0, rowB0};
        #pragma unroll
        for (int arr = 0; arr < 4; arr++) {
            #pragma unroll
            for (int t = 0; t < 4; t++) {
                int u = t * 256 + tid;
                int r = u >> 3, c = u & 7;
                cp_async16(s + arr * GARR + r * GROWB + c * 16,
                           ptrs[arr] + (size_t)(rows[arr] + r) * K + k0 + c * 8);
            }
        }
    };

    #pragma unroll
    for (int s = 0; s < GSTAGES; s++) { load_stage(s, s); CP_COMMIT(); }

    uint32_t ah[2][4][4], al[2][4][4], bh[2][4][2], bl[2][4][2];

    for (int i = 0; i < nchunks; i++) {
        CP_WAIT(GSTAGES - 1);
        __syncthreads();

        const int stage = i % GSTAGES;
        const uint32_t sAhi = sb + stage * GSTAGE;
        const uint32_t sAlo = sAhi + GARR;
        const uint32_t sBhi = sAlo + GARR;
        const uint32_t sBlo = sBhi + GARR;

        // frag loader for sub-step ks into buffer slot
        auto load_frags = [&](int ks, int slot) {
            const int kb = ks * 32;
            #pragma unroll
            for (int mt = 0; mt < 4; mt++) {
                uint32_t aoff = (uint32_t)(warp_m * 64 + mt * 16 + a_lr) * GROWB + a_kc * 2 + kb;
                ldmatrix_x4(ah[slot][mt], sAhi + aoff);
                ldmatrix_x4(al[slot][mt], sAlo + aoff);
            }
            #pragma unroll
            for (int nt = 0; nt < 4; nt++) {
                uint32_t boff = (uint32_t)(warp_n * 32 + nt * 8 + b_lr) * GROWB + b_kc * 2 + kb;
                ldmatrix_x2(bh[slot][nt], sBhi + boff);
                ldmatrix_x2(bl[slot][nt], sBlo + boff);
            }
        };

        load_frags(0, 0);
        #pragma unroll
        for (int ks = 0; ks < 4; ks++) {
            const int cur = ks & 1;
            if (ks < 3) load_frags(ks + 1, cur ^ 1);
            #pragma unroll
            for (int mt = 0; mt < 4; mt++)
                #pragma unroll
                for (int nt = 0; nt < 4; nt++) {
                    mma_bf16(acc[mt][nt], ah[cur][mt], bh[cur][nt]);
                    mma_bf16(acc[mt][nt], ah[cur][mt], bl[cur][nt]);
                    mma_bf16(acc[mt][nt], al[cur][mt], bh[cur][nt]);
                }
        }
        __syncthreads();
        if (i + GSTAGES < nchunks) load_stage(i + GSTAGES, stage);
        CP_COMMIT();
    }
}

// Generic GEMM (O projection): C[M,N] row stride N
__global__ void __launch_bounds__(256, 1)
gemm_bf16x3_kernel(const __nv_bfloat16* __restrict__ Ahi,
                   const __nv_bfloat16* __restrict__ Alo,
                   const __nv_bfloat16* __restrict__ Bhi,
                   const __nv_bfloat16* __restrict__ Blo,
                   const float* __restrict__ bias,
                   float* __restrict__ C,
                   int M, int N, int K)
{
    extern __shared__ char smem[];
    const uint32_t sb = smem_to_u32(smem);
    const int tid  = threadIdx.x;
    const int wid  = tid >> 5;
    const int lane = tid & 31;
    const int rowA0 = blockIdx.y * 128;
    const int rowB0 = blockIdx.x * 128;

    float acc[4][4][4];
    #pragma unroll
    for (int i = 0; i < 4; i++)
        #pragma unroll
        for (int j = 0; j < 4; j++)
            #pragma unroll
            for (int k = 0; k < 4; k++) acc[i][j][k] = 0.0f;

    gemm_mainloop(Ahi, Alo, Bhi, Blo, rowA0, rowB0, K, sb, tid, acc);

    const int warp_m = wid >> 2, warp_n = wid & 3;
    #pragma unroll
    for (int mt = 0; mt < 4; mt++)
        #pragma unroll
        for (int nt = 0; nt < 4; nt++) {
            int row = rowA0 + warp_m * 64 + mt * 16 + (lane >> 2);
            int col = rowB0 + warp_n * 32 + nt * 8 + (lane & 3) * 2;
            float2 b01 = *(const float2*)&bias[col];
            float2 o0 = {acc[mt][nt][0] + b01.x, acc[mt][nt][1] + b01.y};
            float2 o1 = {acc[mt][nt][2] + b01.x, acc[mt][nt][3] + b01.y};
            *(float2*)&C[(size_t)row * N + col]       = o0;
            *(float2*)&C[(size_t)(row + 8) * N + col] = o1;
        }
}

// Fused QKV projection: writes into QKV buffer [M][3072]
__global__ void __launch_bounds__(256, 1)
gemm_qkv_kernel(const __nv_bfloat16* __restrict__ xhi,
                const __nv_bfloat16* __restrict__ xlo,
                const __nv_bfloat16* __restrict__ wqh, const __nv_bfloat16* __restrict__ wql,
                const __nv_bfloat16* __restrict__ wkh, const __nv_bfloat16* __restrict__ wkl,
                const __nv_bfloat16* __restrict__ wvh, const __nv_bfloat16* __restrict__ wvl,
                const float* __restrict__ bq, const float* __restrict__ bk,
                const float* __restrict__ bv,
                float* __restrict__ C)
{
    extern __shared__ char smem[];
    const uint32_t sb = smem_to_u32(smem);
    const int tid  = threadIdx.x;
    const int wid  = tid >> 5;
    const int lane = tid & 31;
    const int cCol = blockIdx.x;         // 0..23
    const int rowA0 = blockIdx.y * 128;

    const __nv_bfloat16 *Bh, *Bl;
    const float* bias;
    int rowB0;
    if (cCol < 16)      { Bh = wqh; Bl = wql; bias = bq; rowB0 = cCol * 128; }
    else if (cCol < 20) { Bh = wkh; Bl = wkl; bias = bk; rowB0 = (cCol - 16) * 128; }
    else                { Bh = wvh; Bl = wvl; bias = bv; rowB0 = (cCol - 20) * 128; }

    float acc[4][4][4];
    #pragma unroll
    for (int i = 0; i < 4; i++)
        #pragma unroll
        for (int j = 0; j < 4; j++)
            #pragma unroll
            for (int k = 0; k < 4; k++) acc[i][j][k] = 0.0f;

    gemm_mainloop(xhi, xlo, Bh, Bl, rowA0, rowB0, E_, sb, tid, acc);

    const int warp_m = wid >> 2, warp_n = wid & 3;
    #pragma unroll
    for (int mt = 0; mt < 4; mt++)
        #pragma unroll
        for (int nt = 0; nt < 4; nt++) {
            int row  = rowA0 + warp_m * 64 + mt * 16 + (lane >> 2);
            int bcol = rowB0 + warp_n * 32 + nt * 8 + (lane & 3) * 2;        // within bias
            int col  = cCol * 128 + warp_n * 32 + nt * 8 + (lane & 3) * 2;   // within QKV
            float2 b01 = *(const float2*)&bias[bcol];
            float2 o0 = {acc[mt][nt][0] + b01.x, acc[mt][nt][1] + b01.y};
            float2 o1 = {acc[mt][nt][2] + b01.x, acc[mt][nt][3] + b01.y};
            *(float2*)&C[(size_t)row * NQKV + col]       = o0;
            *(float2*)&C[(size_t)(row + 8) * NQKV + col] = o1;
        }
}

// ---------------------------------------------------------------------------
// Flash attention, split-bf16 HMMA. Br=128, Bc=64, HD=128, 8 warps.
// ---------------------------------------------------------------------------
#define FROWB  272
#define QARR   (128 * FROWB)        // 34816
#define KARR   (64 * FROWB)         // 17408
#define FSTG   (4 * KARR)           // 69632 (Kh,Kl,Vh,Vl)
#define FSMEM  (2 * QARR + 2 * FSTG)  // 208896

__global__ void __launch_bounds__(256, 1)
flash_mma_kernel(const __nv_bfloat16* __restrict__ Qh, const __nv_bfloat16* __restrict__ Ql,
                 const __nv_bfloat16* __restrict__ Kh, const __nv_bfloat16* __restrict__ Kl,
                 const __nv_bfloat16* __restrict__ Vh, const __nv_bfloat16* __restrict__ Vl,
                 __nv_bfloat16* __restrict__ Ohi, __nv_bfloat16* __restrict__ Olo)
{
    extern __shared__ char smem[];
    const uint32_t sb = smem_to_u32(smem);
    const int tid  = threadIdx.x;
    const int lane = tid & 31;
    const int warp = tid >> 5;
    const int qt = (int)gridDim.x - 1 - (int)blockIdx.x;   // heavy tiles first
    const int h = blockIdx.y, b = blockIdx.z;
    const int g  = h >> 2;
    const int q0 = qt * 128;
    const int nkv = 2 * qt + 2;

    const uint32_t sQh = sb, sQl = sb + QARR;
    const uint32_t sKV0 = sb + 2 * QARR;

    const size_t qbase  = ((size_t)(b * H_ + h) * S_ + q0) * HD_;
    const size_t kvbase = ((size_t)(b * KVH_ + g) * S_) * HD_;

    const uint32_t q_off = (uint32_t)(lane & 15) * FROWB + (lane >> 4) * 16;
    const uint32_t k_off = (uint32_t)((lane & 7) | ((lane >> 1) & 8)) * FROWB + ((lane >> 3) & 1) * 16;

    // -- prologue: Q tile (128 rows) + KV stage 0 --
    #pragma unroll
    for (int t = 0; t < 8; t++) {
        int u = t * 256 + tid;                  // 0..2047
        int r = u >> 4, cb = (u & 15) * 16, ce = (u & 15) * 8;
        cp_async16(sQh + r * FROWB + cb, Qh + qbase + (size_t)r * HD_ + ce);
        cp_async16(sQl + r * FROWB + cb, Ql + qbase + (size_t)r * HD_ + ce);
    }
    auto load_kv = [&](int kt, int buf) {
        uint32_t s = sKV0 + buf * FSTG;
        const size_t base = kvbase + (size_t)kt * 64 * HD_;
        #pragma unroll
        for (int t = 0; t < 4; t++) {
            int u = t * 256 + tid;              // 0..1023
            int r = u >> 4, cb = (u & 15) * 16, ce = (u & 15) * 8;
            size_t go = base + (size_t)r * HD_ + ce;
            uint32_t so = r * FROWB + cb;
            cp_async16(s + so,            Kh + go);
            cp_async16(s + KARR + so,     Kl + go);
            cp_async16(s + 2 * KARR + so, Vh + go);
            cp_async16(s + 3 * KARR + so, Vl + go);
        }
    };
    load_kv(0, 0);
    CP_COMMIT();

    float oacc[16][4];
    #pragma unroll
    for (int i = 0; i < 16; i++)
        #pragma unroll
        for (int j = 0; j < 4; j++) oacc[i][j] = 0.0f;
    float m0 = -INFINITY, m1 = -INFINITY, l0 = 0.0f, l1 = 0.0f;

    for (int kt = 0; kt < nkv; kt++) {
        __syncthreads();
        if (kt + 1 < nkv) { load_kv(kt + 1, (kt + 1) & 1); CP_COMMIT(); CP_WAIT(1); }
        else              { CP_WAIT(0); }
        __syncthreads();

        const uint32_t st  = sKV0 + (kt & 1) * FSTG;
        const uint32_t sKh = st, sKl = st + KARR, sVh = st + 2 * KARR, sVl = st + 3 * KARR;

        // ---- S = Q K^T ----
        float sacc[8][4];
        #pragma unroll
        for (int i = 0; i < 8; i++)
            #pragma unroll
            for (int j = 0; j < 4; j++) sacc[i][j] = 0.0f;

        #pragma unroll
        for (int kk = 0; kk < 8; kk++) {
            const uint32_t kb = kk * 32;
            uint32_t qh[4], ql[4];
            ldmatrix_x4(qh, sQh + (uint32_t)warp * 16 * FROWB + q_off + kb);
            ldmatrix_x4(ql, sQl + (uint32_t)warp * 16 * FROWB + q_off + kb);
            #pragma unroll
            for (int np = 0; np < 4; np++) {
                uint32_t kh[4], kl[4];
                ldmatrix_x4(kh, sKh + (uint32_t)np * 16 * FROWB + k_off + kb);
                ldmatrix_x4(kl, sKl + (uint32_t)np * 16 * FROWB + k_off + kb);
                mma_bf16(sacc[2*np],   qh, &kh[0]);
                mma_bf16(sacc[2*np],   qh, &kl[0]);
                mma_bf16(sacc[2*np],   ql, &kh[0]);
                mma_bf16(sacc[2*np+1], qh, &kh[2]);
                mma_bf16(sacc[2*np+1], qh, &kl[2]);
                mma_bf16(sacc[2*np+1], ql, &kh[2]);
            }
        }

        // ---- causal mask (diagonal region spans kv chunks 2qt, 2qt+1) ----
        if (kt >= 2 * qt) {
            const int rg0 = q0 + warp * 16 + (lane >> 2);
            const int cg0 = kt * 64 + (lane & 3) * 2;
            #pragma unroll
            for (int nt = 0; nt < 8; nt++)
                #pragma unroll
                for (int j = 0; j < 4; j++) {
                    int col = cg0 + nt * 8 + (j & 1);
                    int row = rg0 + (j >> 1) * 8;
                    if (col > row) sacc[nt][j] = -INFINITY;
                }
        }

        // ---- online softmax ----
        float mx0 = -INFINITY, mx1 = -INFINITY;
        #pragma unroll
        for (int nt = 0; nt < 8; nt++) {
            mx0 = fmaxf(mx0, fmaxf(sacc[nt][0], sacc[nt][1]));
            mx1 = fmaxf(mx1, fmaxf(sacc[nt][2], sacc[nt][3]));
        }
        mx0 = fmaxf(mx0, __shfl_xor_sync(0xFFFFFFFF, mx0, 1));
        mx0 = fmaxf(mx0, __shfl_xor_sync(0xFFFFFFFF, mx0, 2));
        mx1 = fmaxf(mx1, __shfl_xor_sync(0xFFFFFFFF, mx1, 1));
        mx1 = fmaxf(mx1, __shfl_xor_sync(0xFFFFFFFF, mx1, 2));
        float mn0 = fmaxf(m0, mx0), mn1 = fmaxf(m1, mx1);
        float al0 = __expf(m0 - mn0), al1 = __expf(m1 - mn1);
        m0 = mn0; m1 = mn1;

        float ps0 = 0.0f, ps1 = 0.0f;
        #pragma unroll
        for (int nt = 0; nt < 8; nt++) {
            float p0 = __expf(sacc[nt][0] - mn0);
            float p1 = __expf(sacc[nt][1] - mn0);
            float p2 = __expf(sacc[nt][2] - mn1);
            float p3 = __expf(sacc[nt][3] - mn1);
            sacc[nt][0] = p0; sacc[nt][1] = p1; sacc[nt][2] = p2; sacc[nt][3] = p3;
            ps0 += p0 + p1; ps1 += p2 + p3;
        }
        ps0 += __shfl_xor_sync(0xFFFFFFFF, ps0, 1);
        ps0 += __shfl_xor_sync(0xFFFFFFFF, ps0, 2);
        ps1 += __shfl_xor_sync(0xFFFFFFFF, ps1, 1);
        ps1 += __shfl_xor_sync(0xFFFFFFFF, ps1, 2);
        l0 = l0 * al0 + ps0;
        l1 = l1 * al1 + ps1;

        #pragma unroll
        for (int i = 0; i < 16; i++) {
            oacc[i][0] *= al0; oacc[i][1] *= al0;
            oacc[i][2] *= al1; oacc[i][3] *= al1;
        }

        // ---- O += P V ----
        #pragma unroll
        for (int tk = 0; tk < 4; tk++) {
            uint32_t ah[4], al_[4];
            split2(sacc[2*tk][0],   sacc[2*tk][1],   ah[0], al_[0]);
            split2(sacc[2*tk][2],   sacc[2*tk][3],   ah[1], al_[1]);
            split2(sacc[2*tk+1][0], sacc[2*tk+1][1], ah[2], al_[2]);
            split2(sacc[2*tk+1][2], sacc[2*tk+1][3], ah[3], al_[3]);
            #pragma unroll
            for (int dp = 0; dp < 8; dp++) {
                uint32_t vh[4], vl[4];
                const uint32_t vo = (uint32_t)tk * 16 * FROWB + q_off + dp * 32;
                ldmatrix_x4_trans(vh, sVh + vo);
                ldmatrix_x4_trans(vl, sVl + vo);
                mma_bf16(oacc[2*dp],   ah,  &vh[0]);
                mma_bf16(oacc[2*dp],   ah,  &vl[0]);
                mma_bf16(oacc[2*dp],   al_, &vh[0]);
                mma_bf16(oacc[2*dp+1], ah,  &vh[2]);
                mma_bf16(oacc[2*dp+1], ah,  &vl[2]);
                mma_bf16(oacc[2*dp+1], al_, &vh[2]);
            }
        }
    }

    // ---- epilogue: O / l -> hi/lo bf16 at [b][s][h*HD] ----
    const float il0 = 1.0f / l0, il1 = 1.0f / l1;
    const int r0 = q0 + warp * 16 + (lane >> 2);
    const int c0 = h * HD_ + (lane & 3) * 2;
    #pragma unroll
    for (int nt = 0; nt < 16; nt++) {
        float o0 = oacc[nt][0] * il0, o1 = oacc[nt][1] * il0;
        float o2 = oacc[nt][2] * il1, o3 = oacc[nt][3] * il1;
        uint32_t h0, l0r, h1, l1r;
        split2(o0, o1, h0, l0r);
        split2(o2, o3, h1, l1r);
        size_t i0 = (size_t)(b * S_ + r0)     * E_ + c0 + nt * 8;
        size_t i1 = (size_t)(b * S_ + r0 + 8) * E_ + c0 + nt * 8;
        *(uint32_t*)(Ohi + i0) = h0; *(uint32_t*)(Olo + i0) = l0r;
        *(uint32_t*)(Ohi + i1) = h1; *(uint32_t*)(Olo + i1) = l1r;
    }
}

// ---------------------------------------------------------------------------
extern "C" void kernel_launch(void* const* d_in, const int* in_sizes, int n_in,
                              void* d_out, int out_size)
{
    const float* x  = (const float*)d_in[0];
    const float* wq = (const float*)d_in[1];
    const float* bq = (const float*)d_in[2];
    const float* wk = (const float*)d_in[3];
    const float* bk = (const float*)d_in[4];
    const float* wv = (const float*)d_in[5];
    const float* bv = (const float*)d_in[6];
    const float* wo = (const float*)d_in[7];
    const float* bo = (const float*)d_in[8];
    float* out = (float*)d_out;

    float* QKVp;
    cudaGetSymbolAddress((void**)&QKVp, g_QKV);
    __nv_bfloat16 *xhi, *xlo, *aohi, *aolo;
    __nv_bfloat16 *wqh, *wql, *wkh, *wkl, *wvh, *wvl, *woh, *wol;
    __nv_bfloat16 *qbh, *qbl, *kbh, *kbl, *vbh, *vbl;
    cudaGetSymbolAddress((void**)&xhi,  g_xhi);
    cudaGetSymbolAddress((void**)&xlo,  g_xlo);
    cudaGetSymbolAddress((void**)&aohi, g_aohi);
    cudaGetSymbolAddress((void**)&aolo, g_aolo);
    cudaGetSymbolAddress((void**)&wqh, g_wqT_hi);
    cudaGetSymbolAddress((void**)&wql, g_wqT_lo);
    cudaGetSymbolAddress((void**)&wkh, g_wkT_hi);
    cudaGetSymbolAddress((void**)&wkl, g_wkT_lo);
    cudaGetSymbolAddress((void**)&wvh, g_wvT_hi);
    cudaGetSymbolAddress((void**)&wvl, g_wvT_lo);
    cudaGetSymbolAddress((void**)&woh, g_woT_hi);
    cudaGetSymbolAddress((void**)&wol, g_woT_lo);
    cudaGetSymbolAddress((void**)&qbh, g_Qbh);
    cudaGetSymbolAddress((void**)&qbl, g_Qbl);
    cudaGetSymbolAddress((void**)&kbh, g_Kbh);
    cudaGetSymbolAddress((void**)&kbl, g_Kbl);
    cudaGetSymbolAddress((void**)&vbh, g_Vbh);
    cudaGetSymbolAddress((void**)&vbl, g_Vbl);

    cudaFuncSetAttribute(gemm_qkv_kernel,
                         cudaFuncAttributeMaxDynamicSharedMemorySize, GSMEM);
    cudaFuncSetAttribute(gemm_bf16x3_kernel,
                         cudaFuncAttributeMaxDynamicSharedMemorySize, GSMEM);
    cudaFuncSetAttribute(flash_mma_kernel,
                         cudaFuncAttributeMaxDynamicSharedMemorySize, FSMEM);

    // launches 1-4: convert + Q/K/V weight transposes (wo transpose deferred)
    {
        int n4 = M_ * E_ / 4;
        convert_hilo_kernel<<<(n4 + 255) / 256, 256>>>(x, xhi, xlo, n4);
        dim3 blk(32, 8);
        transpose_hilo_kernel<<<dim3(E_ / 32, E_ / 32), blk>>>(wq, wqh, wql, E_, E_);
        transpose_hilo_kernel<<<dim3((KVH_ * HD_) / 32, E_ / 32), blk>>>(wk, wkh, wkl, E_, KVH_ * HD_);
        transpose_hilo_kernel<<<dim3((KVH_ * HD_) / 32, E_ / 32), blk>>>(wv, wvh, wvl, E_, KVH_ * HD_);
    }

    // launch 5: fused QKV projection (ncu capture target)
    gemm_qkv_kernel<<<dim3(NQKV / 128, M_ / 128), 256, GSMEM>>>(
        xhi, xlo, wqh, wql, wkh, wkl, wvh, wvl, bq, bk, bv, QKVp);

    // RoPE + split + relayout (reads QKV buffer)
    {
        int totq = B_ * S_ * H_ * (HD_ / 2);
        int totk = B_ * S_ * KVH_ * (HD_ / 2);
        float qscale = 1.0f / sqrtf((float)HD_);
        rope_split_kernel<<<(totq + 255) / 256, 256>>>(QKVp, qbh, qbl, H_, qscale);
        rope_split_kernel<<<(totk + 255) / 256, 256>>>(QKVp + 2048, kbh, kbl, KVH_, 1.0f);
        v_split_kernel<<<(totk + 255) / 256, 256>>>(QKVp + 2560, vbh, vbl);
    }

    // Flash attention (HMMA split-bf16, Br=128)
    flash_mma_kernel<<<dim3(S_ / 128, H_, B_), 256, FSMEM>>>(
        qbh, qbl, kbh, kbl, vbh, vbl, aohi, aolo);

    // wo transpose (deferred; independent of everything before O-proj)
    {
        dim3 blk(32, 8);
        transpose_hilo_kernel<<<dim3(E_ / 32, E_ / 32), blk>>>(wo, woh, wol, E_, E_);
    }

    // Output projection -> d_out
    gemm_bf16x3_kernel<<<dim3(E_ / 128, M_ / 128), 256, GSMEM>>>(
        aohi, aolo, woh, wol, bo, out, M_, E_, E_);
}

// round 10
// speedup vs baseline: 1.0904x; 1.0017x over previous
#include <cuda_runtime.h>
#include <cuda_bf16.h>
#include <math.h>
#include <cstdint>

#define B_   2
#define S_   2048
#define E_   2048
#define H_   16
#define KVH_ 4
#define HD_  128
#define REP_ 4
#define M_   (B_*S_)     // 4096
#define NQKV 3072        // 2048 Q + 512 K + 512 V

// ---------------------------------------------------------------------------
// Scratch (__device__ globals; no allocations allowed)
// ---------------------------------------------------------------------------
__device__ float g_QKV[M_*NQKV];

__device__ __nv_bfloat16 g_xhi[M_*E_],  g_xlo[M_*E_];
__device__ __nv_bfloat16 g_aohi[M_*E_], g_aolo[M_*E_];
__device__ __nv_bfloat16 g_wqT_hi[E_*E_],        g_wqT_lo[E_*E_];
__device__ __nv_bfloat16 g_wkT_hi[KVH_*HD_*E_],  g_wkT_lo[KVH_*HD_*E_];
__device__ __nv_bfloat16 g_wvT_hi[KVH_*HD_*E_],  g_wvT_lo[KVH_*HD_*E_];
__device__ __nv_bfloat16 g_woT_hi[E_*E_],        g_woT_lo[E_*E_];

// flash operand layouts: Q [B][H][S][HD], K/V [B][KVH][S][HD]
__device__ __nv_bfloat16 g_Qbh[M_*H_*HD_],   g_Qbl[M_*H_*HD_];
__device__ __nv_bfloat16 g_Kbh[M_*KVH_*HD_], g_Kbl[M_*KVH_*HD_];
__device__ __nv_bfloat16 g_Vbh[M_*KVH_*HD_], g_Vbl[M_*KVH_*HD_];

// ---------------------------------------------------------------------------
// PTX helpers (non-'a' ISA only: mma.sync / ldmatrix / cp.async)
// ---------------------------------------------------------------------------
__device__ __forceinline__ uint32_t smem_to_u32(const void* p) {
    uint32_t a;
    asm("{ .reg .u64 t; cvta.to.shared.u64 t, %1; cvt.u32.u64 %0, t; }" : "=r"(a) : "l"(p));
    return a;
}
__device__ __forceinline__ void cp_async16(uint32_t saddr, const void* gptr) {
    asm volatile("cp.async.cg.shared.global [%0], [%1], 16;\n" :: "r"(saddr), "l"(gptr));
}
#define CP_COMMIT() asm volatile("cp.async.commit_group;\n" ::: "memory")
#define CP_WAIT(n)  asm volatile("cp.async.wait_group %0;\n" :: "n"(n) : "memory")

__device__ __forceinline__ void ldmatrix_x4(uint32_t* r, uint32_t addr) {
    asm volatile("ldmatrix.sync.aligned.m8n8.x4.shared.b16 {%0,%1,%2,%3}, [%4];\n"
                 : "=r"(r[0]), "=r"(r[1]), "=r"(r[2]), "=r"(r[3]) : "r"(addr));
}
__device__ __forceinline__ void ldmatrix_x4_trans(uint32_t* r, uint32_t addr) {
    asm volatile("ldmatrix.sync.aligned.m8n8.x4.trans.shared.b16 {%0,%1,%2,%3}, [%4];\n"
                 : "=r"(r[0]), "=r"(r[1]), "=r"(r[2]), "=r"(r[3]) : "r"(addr));
}
__device__ __forceinline__ void ldmatrix_x2(uint32_t* r, uint32_t addr) {
    asm volatile("ldmatrix.sync.aligned.m8n8.x2.shared.b16 {%0,%1}, [%2];\n"
                 : "=r"(r[0]), "=r"(r[1]) : "r"(addr));
}
__device__ __forceinline__ void mma_bf16(float* c, const uint32_t* a, const uint32_t* b) {
    asm volatile(
        "mma.sync.aligned.m16n8k16.row.col.f32.bf16.bf16.f32 "
        "{%0,%1,%2,%3}, {%4,%5,%6,%7}, {%8,%9}, {%0,%1,%2,%3};\n"
        : "+f"(c[0]), "+f"(c[1]), "+f"(c[2]), "+f"(c[3])
        : "r"(a[0]), "r"(a[1]), "r"(a[2]), "r"(a[3]), "r"(b[0]), "r"(b[1]));
}
__device__ __forceinline__ void split2(float a, float b, uint32_t& hi, uint32_t& lo) {
    __nv_bfloat162 h = __floats2bfloat162_rn(a, b);
    __nv_bfloat162 l = __floats2bfloat162_rn(a - __bfloat162float(h.x),
                                             b - __bfloat162float(h.y));
    hi = *(uint32_t*)&h;
    lo = *(uint32_t*)&l;
}

// ---------------------------------------------------------------------------
// Conversion kernels
// ---------------------------------------------------------------------------
__global__ void convert_hilo_kernel(const float* __restrict__ in,
                                    __nv_bfloat16* __restrict__ hi,
                                    __nv_bfloat16* __restrict__ lo, int n4)
{
    int i = blockIdx.x * blockDim.x + threadIdx.x;
    if (i >= n4) return;
    float4 v = ((const float4*)in)[i];
    float a[4] = {v.x, v.y, v.z, v.w};
    __nv_bfloat16 h[4], l[4];
    #pragma unroll
    for (int j = 0; j < 4; j++) {
        h[j] = __float2bfloat16_rn(a[j]);
        l[j] = __float2bfloat16_rn(a[j] - __bfloat162float(h[j]));
    }
    __nv_bfloat162* ph = (__nv_bfloat162*)(hi + 4 * (size_t)i);
    __nv_bfloat162* pl = (__nv_bfloat162*)(lo + 4 * (size_t)i);
    ph[0] = __nv_bfloat162{h[0], h[1]}; ph[1] = __nv_bfloat162{h[2], h[3]};
    pl[0] = __nv_bfloat162{l[0], l[1]}; pl[1] = __nv_bfloat162{l[2], l[3]};
}

// W[K x N] fp32 -> WT_hi/lo[N x K] bf16
__global__ void transpose_hilo_kernel(const float* __restrict__ W,
                                      __nv_bfloat16* __restrict__ Thi,
                                      __nv_bfloat16* __restrict__ Tlo,
                                      int K, int N)
{
    __shared__ float tile[32][33];
    int n0 = blockIdx.x * 32, k0 = blockIdx.y * 32;
    int tx = threadIdx.x, ty = threadIdx.y;
    #pragma unroll
    for (int r = 0; r < 4; r++)
        tile[ty + r * 8][tx] = W[(size_t)(k0 + ty + r * 8) * N + n0 + tx];
    __syncthreads();
    #pragma unroll
    for (int r = 0; r < 4; r++) {
        float v = tile[tx][ty + r * 8];
        __nv_bfloat16 h = __float2bfloat16_rn(v);
        __nv_bfloat16 l = __float2bfloat16_rn(v - __bfloat162float(h));
        size_t o = (size_t)(n0 + ty + r * 8) * K + k0 + tx;
        Thi[o] = h; Tlo[o] = l;
    }
}

// RoPE + hi/lo split; src = QKV buffer (row stride NQKV, col base h*HD)
__global__ void rope_split_kernel(const float* __restrict__ in,
                                  __nv_bfloat16* __restrict__ outh,
                                  __nv_bfloat16* __restrict__ outl,
                                  int nh, float scale)
{
    int idx = blockIdx.x * blockDim.x + threadIdx.x;
    int total = B_ * S_ * nh * (HD_ / 2);
    if (idx >= total) return;
    int d2 = idx & 63;
    int h  = (idx >> 6) % nh;
    int s  = (idx / (64 * nh)) % S_;
    int b  = idx / (64 * nh * S_);
    float p    = powf(100000.0f, (float)(2 * d2));   // inf for 2*d2 >= 8
    float freq = 1.0f / p;                           // 0 when p == inf
    float ang  = (float)s * freq;
    float sn, cs;
    sincosf(ang, &sn, &cs);
    size_t src = (size_t)(b * S_ + s) * NQKV + h * HD_ + 2 * d2;
    float tr = in[src], ti = in[src + 1];
    float o0 = (tr * cs - ti * sn) * scale;
    float o1 = (tr * sn + ti * cs) * scale;
    uint32_t hi, lo;
    split2(o0, o1, hi, lo);
    size_t dst = ((size_t)(b * nh + h) * S_ + s) * HD_ + 2 * d2;
    *(uint32_t*)(outh + dst) = hi;
    *(uint32_t*)(outl + dst) = lo;
}

// V: hi/lo split + relayout from QKV buffer
__global__ void v_split_kernel(const float* __restrict__ in,
                               __nv_bfloat16* __restrict__ outh,
                               __nv_bfloat16* __restrict__ outl)
{
    int idx = blockIdx.x * blockDim.x + threadIdx.x;
    int total = B_ * S_ * KVH_ * (HD_ / 2);
    if (idx >= total) return;
    int d2 = idx & 63;
    int g  = (idx >> 6) % KVH_;
    int s  = (idx / (64 * KVH_)) % S_;
    int b  = idx / (64 * KVH_ * S_);
    size_t src = (size_t)(b * S_ + s) * NQKV + g * HD_ + 2 * d2;
    float2 v = *(const float2*)(in + src);
    uint32_t hi, lo;
    split2(v.x, v.y, hi, lo);
    size_t dst = ((size_t)(b * KVH_ + g) * S_ + s) * HD_ + 2 * d2;
    *(uint32_t*)(outh + dst) = hi;
    *(uint32_t*)(outl + dst) = lo;
}

// ---------------------------------------------------------------------------
// Split-bf16 HMMA GEMM mainloop: 128x128 tile, K chunks of 64, 3 stages,
// SINGLE __syncthreads per chunk (CUTLASS multistage pattern):
//   wait(S-2); sync; issue load(i+S-1); MMAs(i)
// The one barrier publishes stage i AND proves all warps finished stage i-1,
// making the slot overwrite safe.
// ---------------------------------------------------------------------------
#define GBK      64
#define GROWB    144                   // 128B data + 16 pad
#define GARR     (128 * GROWB)         // 18432
#define GSTAGE   (4 * GARR)            // 73728
#define GSTAGES  3
#define GSMEM    (GSTAGES * GSTAGE)    // 221184

__device__ __forceinline__ void gemm_mainloop(
    const __nv_bfloat16* __restrict__ Ahi, const __nv_bfloat16* __restrict__ Alo,
    const __nv_bfloat16* __restrict__ Bhi, const __nv_bfloat16* __restrict__ Blo,
    int rowA0, int rowB0, int K, uint32_t sb, int tid, float acc[4][4][4])
{
    const int wid  = tid >> 5;
    const int lane = tid & 31;
    const int warp_m = wid >> 2;
    const int warp_n = wid & 3;
    const int nchunks = K / GBK;

    const int a_lr = lane & 15;
    const int a_kc = (lane >> 4) * 8;
    const int b_lr = lane & 7;
    const int b_kc = ((lane >> 3) & 3) * 8;

    auto load_stage = [&](int chunk, int stage) {
        const int k0 = chunk * GBK;
        uint32_t s = sb + stage * GSTAGE;
        const __nv_bfloat16* ptrs[4] = {Ahi, Alo, Bhi, Blo};
        const int rows[4] = {rowA0, rowA0, rowB0, rowB0};
        #pragma unroll
        for (int arr = 0; arr < 4; arr++) {
            #pragma unroll
            for (int t = 0; t < 4; t++) {
                int u = t * 256 + tid;
                int r = u >> 3, c = u & 7;
                cp_async16(s + arr * GARR + r * GROWB + c * 16,
                           ptrs[arr] + (size_t)(rows[arr] + r) * K + k0 + c * 8);
            }
        }
    };

    // prologue: stages 0 .. S-2
    #pragma unroll
    for (int s = 0; s < GSTAGES - 1; s++) { load_stage(s, s); CP_COMMIT(); }

    uint32_t ah[2][4][4], al[2][4][4], bh[2][4][2], bl[2][4][2];

    for (int i = 0; i < nchunks; i++) {
        CP_WAIT(GSTAGES - 2);      // stage i arrived
        __syncthreads();           // publish stage i; all warps done with stage i-1

        // issue next stage load before compute (slot (i+S-1)%S == slot (i-1)%S, now free)
        if (i + GSTAGES - 1 < nchunks)
            load_stage(i + GSTAGES - 1, (i + GSTAGES - 1) % GSTAGES);
        CP_COMMIT();

        const int stage = i % GSTAGES;
        const uint32_t sAhi = sb + stage * GSTAGE;
        const uint32_t sAlo = sAhi + GARR;
        const uint32_t sBhi = sAlo + GARR;
        const uint32_t sBlo = sBhi + GARR;

        auto load_frags = [&](int ks, int slot) {
            const int kb = ks * 32;
            #pragma unroll
            for (int mt = 0; mt < 4; mt++) {
                uint32_t aoff = (uint32_t)(warp_m * 64 + mt * 16 + a_lr) * GROWB + a_kc * 2 + kb;
                ldmatrix_x4(ah[slot][mt], sAhi + aoff);
                ldmatrix_x4(al[slot][mt], sAlo + aoff);
            }
            #pragma unroll
            for (int nt = 0; nt < 4; nt++) {
                uint32_t boff = (uint32_t)(warp_n * 32 + nt * 8 + b_lr) * GROWB + b_kc * 2 + kb;
                ldmatrix_x2(bh[slot][nt], sBhi + boff);
                ldmatrix_x2(bl[slot][nt], sBlo + boff);
            }
        };

        load_frags(0, 0);
        #pragma unroll
        for (int ks = 0; ks < 4; ks++) {
            const int cur = ks & 1;
            if (ks < 3) load_frags(ks + 1, cur ^ 1);
            #pragma unroll
            for (int mt = 0; mt < 4; mt++)
                #pragma unroll
                for (int nt = 0; nt < 4; nt++) {
                    mma_bf16(acc[mt][nt], ah[cur][mt], bh[cur][nt]);
                    mma_bf16(acc[mt][nt], ah[cur][mt], bl[cur][nt]);
                    mma_bf16(acc[mt][nt], al[cur][mt], bh[cur][nt]);
                }
        }
    }
}

// Generic GEMM (O projection): C[M,N] row stride N
__global__ void __launch_bounds__(256, 1)
gemm_bf16x3_kernel(const __nv_bfloat16* __restrict__ Ahi,
                   const __nv_bfloat16* __restrict__ Alo,
                   const __nv_bfloat16* __restrict__ Bhi,
                   const __nv_bfloat16* __restrict__ Blo,
                   const float* __restrict__ bias,
                   float* __restrict__ C,
                   int M, int N, int K)
{
    extern __shared__ char smem[];
    const uint32_t sb = smem_to_u32(smem);
    const int tid  = threadIdx.x;
    const int wid  = tid >> 5;
    const int lane = tid & 31;
    const int rowA0 = blockIdx.y * 128;
    const int rowB0 = blockIdx.x * 128;

    float acc[4][4][4];
    #pragma unroll
    for (int i = 0; i < 4; i++)
        #pragma unroll
        for (int j = 0; j < 4; j++)
            #pragma unroll
            for (int k = 0; k < 4; k++) acc[i][j][k] = 0.0f;

    gemm_mainloop(Ahi, Alo, Bhi, Blo, rowA0, rowB0, K, sb, tid, acc);

    const int warp_m = wid >> 2, warp_n = wid & 3;
    #pragma unroll
    for (int mt = 0; mt < 4; mt++)
        #pragma unroll
        for (int nt = 0; nt < 4; nt++) {
            int row = rowA0 + warp_m * 64 + mt * 16 + (lane >> 2);
            int col = rowB0 + warp_n * 32 + nt * 8 + (lane & 3) * 2;
            float2 b01 = *(const float2*)&bias[col];
            float2 o0 = {acc[mt][nt][0] + b01.x, acc[mt][nt][1] + b01.y};
            float2 o1 = {acc[mt][nt][2] + b01.x, acc[mt][nt][3] + b01.y};
            *(float2*)&C[(size_t)row * N + col]       = o0;
            *(float2*)&C[(size_t)(row + 8) * N + col] = o1;
        }
}

// Fused QKV projection: writes into QKV buffer [M][3072]
__global__ void __launch_bounds__(256, 1)
gemm_qkv_kernel(const __nv_bfloat16* __restrict__ xhi,
                const __nv_bfloat16* __restrict__ xlo,
                const __nv_bfloat16* __restrict__ wqh, const __nv_bfloat16* __restrict__ wql,
                const __nv_bfloat16* __restrict__ wkh, const __nv_bfloat16* __restrict__ wkl,
                const __nv_bfloat16* __restrict__ wvh, const __nv_bfloat16* __restrict__ wvl,
                const float* __restrict__ bq, const float* __restrict__ bk,
                const float* __restrict__ bv,
                float* __restrict__ C)
{
    extern __shared__ char smem[];
    const uint32_t sb = smem_to_u32(smem);
    const int tid  = threadIdx.x;
    const int wid  = tid >> 5;
    const int lane = tid & 31;
    const int cCol = blockIdx.x;         // 0..23
    const int rowA0 = blockIdx.y * 128;

    const __nv_bfloat16 *Bh, *Bl;
    const float* bias;
    int rowB0;
    if (cCol < 16)      { Bh = wqh; Bl = wql; bias = bq; rowB0 = cCol * 128; }
    else if (cCol < 20) { Bh = wkh; Bl = wkl; bias = bk; rowB0 = (cCol - 16) * 128; }
    else                { Bh = wvh; Bl = wvl; bias = bv; rowB0 = (cCol - 20) * 128; }

    float acc[4][4][4];
    #pragma unroll
    for (int i = 0; i < 4; i++)
        #pragma unroll
        for (int j = 0; j < 4; j++)
            #pragma unroll
            for (int k = 0; k < 4; k++) acc[i][j][k] = 0.0f;

    gemm_mainloop(xhi, xlo, Bh, Bl, rowA0, rowB0, E_, sb, tid, acc);

    const int warp_m = wid >> 2, warp_n = wid & 3;
    #pragma unroll
    for (int mt = 0; mt < 4; mt++)
        #pragma unroll
        for (int nt = 0; nt < 4; nt++) {
            int row  = rowA0 + warp_m * 64 + mt * 16 + (lane >> 2);
            int bcol = rowB0 + warp_n * 32 + nt * 8 + (lane & 3) * 2;        // within bias
            int col  = cCol * 128 + warp_n * 32 + nt * 8 + (lane & 3) * 2;   // within QKV
            float2 b01 = *(const float2*)&bias[bcol];
            float2 o0 = {acc[mt][nt][0] + b01.x, acc[mt][nt][1] + b01.y};
            float2 o1 = {acc[mt][nt][2] + b01.x, acc[mt][nt][3] + b01.y};
            *(float2*)&C[(size_t)row * NQKV + col]       = o0;
            *(float2*)&C[(size_t)(row + 8) * NQKV + col] = o1;
        }
}

// ---------------------------------------------------------------------------
// Flash attention, split-bf16 HMMA. Br=128, Bc=64, HD=128, 8 warps.
// ---------------------------------------------------------------------------
#define FROWB  272
#define QARR   (128 * FROWB)        // 34816
#define KARR   (64 * FROWB)         // 17408
#define FSTG   (4 * KARR)           // 69632 (Kh,Kl,Vh,Vl)
#define FSMEM  (2 * QARR + 2 * FSTG)  // 208896

__global__ void __launch_bounds__(256, 1)
flash_mma_kernel(const __nv_bfloat16* __restrict__ Qh, const __nv_bfloat16* __restrict__ Ql,
                 const __nv_bfloat16* __restrict__ Kh, const __nv_bfloat16* __restrict__ Kl,
                 const __nv_bfloat16* __restrict__ Vh, const __nv_bfloat16* __restrict__ Vl,
                 __nv_bfloat16* __restrict__ Ohi, __nv_bfloat16* __restrict__ Olo)
{
    extern __shared__ char smem[];
    const uint32_t sb = smem_to_u32(smem);
    const int tid  = threadIdx.x;
    const int lane = tid & 31;
    const int warp = tid >> 5;
    const int qt = (int)gridDim.x - 1 - (int)blockIdx.x;   // heavy tiles first
    const int h = blockIdx.y, b = blockIdx.z;
    const int g  = h >> 2;
    const int q0 = qt * 128;
    const int nkv = 2 * qt + 2;

    const uint32_t sQh = sb, sQl = sb + QARR;
    const uint32_t sKV0 = sb + 2 * QARR;

    const size_t qbase  = ((size_t)(b * H_ + h) * S_ + q0) * HD_;
    const size_t kvbase = ((size_t)(b * KVH_ + g) * S_) * HD_;

    const uint32_t q_off = (uint32_t)(lane & 15) * FROWB + (lane >> 4) * 16;
    const uint32_t k_off = (uint32_t)((lane & 7) | ((lane >> 1) & 8)) * FROWB + ((lane >> 3) & 1) * 16;

    // -- prologue: Q tile (128 rows) + KV stage 0 --
    #pragma unroll
    for (int t = 0; t < 8; t++) {
        int u = t * 256 + tid;                  // 0..2047
        int r = u >> 4, cb = (u & 15) * 16, ce = (u & 15) * 8;
        cp_async16(sQh + r * FROWB + cb, Qh + qbase + (size_t)r * HD_ + ce);
        cp_async16(sQl + r * FROWB + cb, Ql + qbase + (size_t)r * HD_ + ce);
    }
    auto load_kv = [&](int kt, int buf) {
        uint32_t s = sKV0 + buf * FSTG;
        const size_t base = kvbase + (size_t)kt * 64 * HD_;
        #pragma unroll
        for (int t = 0; t < 4; t++) {
            int u = t * 256 + tid;              // 0..1023
            int r = u >> 4, cb = (u & 15) * 16, ce = (u & 15) * 8;
            size_t go = base + (size_t)r * HD_ + ce;
            uint32_t so = r * FROWB + cb;
            cp_async16(s + so,            Kh + go);
            cp_async16(s + KARR + so,     Kl + go);
            cp_async16(s + 2 * KARR + so, Vh + go);
            cp_async16(s + 3 * KARR + so, Vl + go);
        }
    };
    load_kv(0, 0);
    CP_COMMIT();

    float oacc[16][4];
    #pragma unroll
    for (int i = 0; i < 16; i++)
        #pragma unroll
        for (int j = 0; j < 4; j++) oacc[i][j] = 0.0f;
    float m0 = -INFINITY, m1 = -INFINITY, l0 = 0.0f, l1 = 0.0f;

    for (int kt = 0; kt < nkv; kt++) {
        __syncthreads();
        if (kt + 1 < nkv) { load_kv(kt + 1, (kt + 1) & 1); CP_COMMIT(); CP_WAIT(1); }
        else              { CP_WAIT(0); }
        __syncthreads();

        const uint32_t st  = sKV0 + (kt & 1) * FSTG;
        const uint32_t sKh = st, sKl = st + KARR, sVh = st + 2 * KARR, sVl = st + 3 * KARR;

        // ---- S = Q K^T ----
        float sacc[8][4];
        #pragma unroll
        for (int i = 0; i < 8; i++)
            #pragma unroll
            for (int j = 0; j < 4; j++) sacc[i][j] = 0.0f;

        #pragma unroll
        for (int kk = 0; kk < 8; kk++) {
            const uint32_t kb = kk * 32;
            uint32_t qh[4], ql[4];
            ldmatrix_x4(qh, sQh + (uint32_t)warp * 16 * FROWB + q_off + kb);
            ldmatrix_x4(ql, sQl + (uint32_t)warp * 16 * FROWB + q_off + kb);
            #pragma unroll
            for (int np = 0; np < 4; np++) {
                uint32_t kh[4], kl[4];
                ldmatrix_x4(kh, sKh + (uint32_t)np * 16 * FROWB + k_off + kb);
                ldmatrix_x4(kl, sKl + (uint32_t)np * 16 * FROWB + k_off + kb);
                mma_bf16(sacc[2*np],   qh, &kh[0]);
                mma_bf16(sacc[2*np],   qh, &kl[0]);
                mma_bf16(sacc[2*np],   ql, &kh[0]);
                mma_bf16(sacc[2*np+1], qh, &kh[2]);
                mma_bf16(sacc[2*np+1], qh, &kl[2]);
                mma_bf16(sacc[2*np+1], ql, &kh[2]);
            }
        }

        // ---- causal mask (diagonal region spans kv chunks 2qt, 2qt+1) ----
        if (kt >= 2 * qt) {
            const int rg0 = q0 + warp * 16 + (lane >> 2);
            const int cg0 = kt * 64 + (lane & 3) * 2;
            #pragma unroll
            for (int nt = 0; nt < 8; nt++)
                #pragma unroll
                for (int j = 0; j < 4; j++) {
                    int col = cg0 + nt * 8 + (j & 1);
                    int row = rg0 + (j >> 1) * 8;
                    if (col > row) sacc[nt][j] = -INFINITY;
                }
        }

        // ---- online softmax ----
        float mx0 = -INFINITY, mx1 = -INFINITY;
        #pragma unroll
        for (int nt = 0; nt < 8; nt++) {
            mx0 = fmaxf(mx0, fmaxf(sacc[nt][0], sacc[nt][1]));
            mx1 = fmaxf(mx1, fmaxf(sacc[nt][2], sacc[nt][3]));
        }
        mx0 = fmaxf(mx0, __shfl_xor_sync(0xFFFFFFFF, mx0, 1));
        mx0 = fmaxf(mx0, __shfl_xor_sync(0xFFFFFFFF, mx0, 2));
        mx1 = fmaxf(mx1, __shfl_xor_sync(0xFFFFFFFF, mx1, 1));
        mx1 = fmaxf(mx1, __shfl_xor_sync(0xFFFFFFFF, mx1, 2));
        float mn0 = fmaxf(m0, mx0), mn1 = fmaxf(m1, mx1);
        float al0 = __expf(m0 - mn0), al1 = __expf(m1 - mn1);
        m0 = mn0; m1 = mn1;

        float ps0 = 0.0f, ps1 = 0.0f;
        #pragma unroll
        for (int nt = 0; nt < 8; nt++) {
            float p0 = __expf(sacc[nt][0] - mn0);
            float p1 = __expf(sacc[nt][1] - mn0);
            float p2 = __expf(sacc[nt][2] - mn1);
            float p3 = __expf(sacc[nt][3] - mn1);
            sacc[nt][0] = p0; sacc[nt][1] = p1; sacc[nt][2] = p2; sacc[nt][3] = p3;
            ps0 += p0 + p1; ps1 += p2 + p3;
        }
        ps0 += __shfl_xor_sync(0xFFFFFFFF, ps0, 1);
        ps0 += __shfl_xor_sync(0xFFFFFFFF, ps0, 2);
        ps1 += __shfl_xor_sync(0xFFFFFFFF, ps1, 1);
        ps1 += __shfl_xor_sync(0xFFFFFFFF, ps1, 2);
        l0 = l0 * al0 + ps0;
        l1 = l1 * al1 + ps1;

        #pragma unroll
        for (int i = 0; i < 16; i++) {
            oacc[i][0] *= al0; oacc[i][1] *= al0;
            oacc[i][2] *= al1; oacc[i][3] *= al1;
        }

        // ---- O += P V ----
        #pragma unroll
        for (int tk = 0; tk < 4; tk++) {
            uint32_t ah[4], al_[4];
            split2(sacc[2*tk][0],   sacc[2*tk][1],   ah[0], al_[0]);
            split2(sacc[2*tk][2],   sacc[2*tk][3],   ah[1], al_[1]);
            split2(sacc[2*tk+1][0], sacc[2*tk+1][1], ah[2], al_[2]);
            split2(sacc[2*tk+1][2], sacc[2*tk+1][3], ah[3], al_[3]);
            #pragma unroll
            for (int dp = 0; dp < 8; dp++) {
                uint32_t vh[4], vl[4];
                const uint32_t vo = (uint32_t)tk * 16 * FROWB + q_off + dp * 32;
                ldmatrix_x4_trans(vh, sVh + vo);
                ldmatrix_x4_trans(vl, sVl + vo);
                mma_bf16(oacc[2*dp],   ah,  &vh[0]);
                mma_bf16(oacc[2*dp],   ah,  &vl[0]);
                mma_bf16(oacc[2*dp],   al_, &vh[0]);
                mma_bf16(oacc[2*dp+1], ah,  &vh[2]);
                mma_bf16(oacc[2*dp+1], ah,  &vl[2]);
                mma_bf16(oacc[2*dp+1], al_, &vh[2]);
            }
        }
    }

    // ---- epilogue: O / l -> hi/lo bf16 at [b][s][h*HD] ----
    const float il0 = 1.0f / l0, il1 = 1.0f / l1;
    const int r0 = q0 + warp * 16 + (lane >> 2);
    const int c0 = h * HD_ + (lane & 3) * 2;
    #pragma unroll
    for (int nt = 0; nt < 16; nt++) {
        float o0 = oacc[nt][0] * il0, o1 = oacc[nt][1] * il0;
        float o2 = oacc[nt][2] * il1, o3 = oacc[nt][3] * il1;
        uint32_t h0, l0r, h1, l1r;
        split2(o0, o1, h0, l0r);
        split2(o2, o3, h1, l1r);
        size_t i0 = (size_t)(b * S_ + r0)     * E_ + c0 + nt * 8;
        size_t i1 = (size_t)(b * S_ + r0 + 8) * E_ + c0 + nt * 8;
        *(uint32_t*)(Ohi + i0) = h0; *(uint32_t*)(Olo + i0) = l0r;
        *(uint32_t*)(Ohi + i1) = h1; *(uint32_t*)(Olo + i1) = l1r;
    }
}

// ---------------------------------------------------------------------------
extern "C" void kernel_launch(void* const* d_in, const int* in_sizes, int n_in,
                              void* d_out, int out_size)
{
    const float* x  = (const float*)d_in[0];
    const float* wq = (const float*)d_in[1];
    const float* bq = (const float*)d_in[2];
    const float* wk = (const float*)d_in[3];
    const float* bk = (const float*)d_in[4];
    const float* wv = (const float*)d_in[5];
    const float* bv = (const float*)d_in[6];
    const float* wo = (const float*)d_in[7];
    const float* bo = (const float*)d_in[8];
    float* out = (float*)d_out;

    float* QKVp;
    cudaGetSymbolAddress((void**)&QKVp, g_QKV);
    __nv_bfloat16 *xhi, *xlo, *aohi, *aolo;
    __nv_bfloat16 *wqh, *wql, *wkh, *wkl, *wvh, *wvl, *woh, *wol;
    __nv_bfloat16 *qbh, *qbl, *kbh, *kbl, *vbh, *vbl;
    cudaGetSymbolAddress((void**)&xhi,  g_xhi);
    cudaGetSymbolAddress((void**)&xlo,  g_xlo);
    cudaGetSymbolAddress((void**)&aohi, g_aohi);
    cudaGetSymbolAddress((void**)&aolo, g_aolo);
    cudaGetSymbolAddress((void**)&wqh, g_wqT_hi);
    cudaGetSymbolAddress((void**)&wql, g_wqT_lo);
    cudaGetSymbolAddress((void**)&wkh, g_wkT_hi);
    cudaGetSymbolAddress((void**)&wkl, g_wkT_lo);
    cudaGetSymbolAddress((void**)&wvh, g_wvT_hi);
    cudaGetSymbolAddress((void**)&wvl, g_wvT_lo);
    cudaGetSymbolAddress((void**)&woh, g_woT_hi);
    cudaGetSymbolAddress((void**)&wol, g_woT_lo);
    cudaGetSymbolAddress((void**)&qbh, g_Qbh);
    cudaGetSymbolAddress((void**)&qbl, g_Qbl);
    cudaGetSymbolAddress((void**)&kbh, g_Kbh);
    cudaGetSymbolAddress((void**)&kbl, g_Kbl);
    cudaGetSymbolAddress((void**)&vbh, g_Vbh);
    cudaGetSymbolAddress((void**)&vbl, g_Vbl);

    cudaFuncSetAttribute(gemm_qkv_kernel,
                         cudaFuncAttributeMaxDynamicSharedMemorySize, GSMEM);
    cudaFuncSetAttribute(gemm_bf16x3_kernel,
                         cudaFuncAttributeMaxDynamicSharedMemorySize, GSMEM);
    cudaFuncSetAttribute(flash_mma_kernel,
                         cudaFuncAttributeMaxDynamicSharedMemorySize, FSMEM);

    // conversions
    {
        int n4 = M_ * E_ / 4;
        convert_hilo_kernel<<<(n4 + 255) / 256, 256>>>(x, xhi, xlo, n4);
        dim3 blk(32, 8);
        transpose_hilo_kernel<<<dim3(E_ / 32, E_ / 32), blk>>>(wq, wqh, wql, E_, E_);
        transpose_hilo_kernel<<<dim3((KVH_ * HD_) / 32, E_ / 32), blk>>>(wk, wkh, wkl, E_, KVH_ * HD_);
        transpose_hilo_kernel<<<dim3((KVH_ * HD_) / 32, E_ / 32), blk>>>(wv, wvh, wvl, E_, KVH_ * HD_);
    }

    // Fused QKV projection (N = 3072)
    gemm_qkv_kernel<<<dim3(NQKV / 128, M_ / 128), 256, GSMEM>>>(
        xhi, xlo, wqh, wql, wkh, wkl, wvh, wvl, bq, bk, bv, QKVp);

    // RoPE + split + relayout (reads QKV buffer)
    {
        int totq = B_ * S_ * H_ * (HD_ / 2);
        int totk = B_ * S_ * KVH_ * (HD_ / 2);
        float qscale = 1.0f / sqrtf((float)HD_);
        rope_split_kernel<<<(totq + 255) / 256, 256>>>(QKVp, qbh, qbl, H_, qscale);
        rope_split_kernel<<<(totk + 255) / 256, 256>>>(QKVp + 2048, kbh, kbl, KVH_, 1.0f);
        v_split_kernel<<<(totk + 255) / 256, 256>>>(QKVp + 2560, vbh, vbl);
    }

    // Flash attention (HMMA split-bf16, Br=128)
    flash_mma_kernel<<<dim3(S_ / 128, H_, B_), 256, FSMEM>>>(
        qbh, qbl, kbh, kbl, vbh, vbl, aohi, aolo);

    // wo transpose (deferred; only needed by O-proj)
    {
        dim3 blk(32, 8);
        transpose_hilo_kernel<<<dim3(E_ / 32, E_ / 32), blk>>>(wo, woh, wol, E_, E_);
    }

    // Output projection -> d_out
    gemm_bf16x3_kernel<<<dim3(E_ / 128, M_ / 128), 256, GSMEM>>>(
        aohi, aolo, woh, wol, bo, out, M_, E_, E_);
}